// round 11
// baseline (speedup 1.0000x reference)
#include <cuda_runtime.h>
#include <cuda_bf16.h>
#include <stdint.h>

#define NU 6041
#define NM 3953
#define B_TOTAL 1048576
#define NTILES 8192          // 128 rows per CTA-tile
#define GRID 592
#define THREADS 128          // 4 warps, 32 rows/warp
#define AW 52                // u32 words per A row

typedef unsigned long long u64;
typedef unsigned int u32;

// ---- dynamic smem offsets (bytes) ----
#define OFF_A1    0u        // 4*32*52*4 = 26624
#define OFF_B1F   26624u    // 12288
#define OFF_B2F   38912u    // 4096
#define OFF_G     43008u    // 4*576*4 = 9216
#define OFF_IDS   52224u    // 4*64*4 = 1024
#define OFF_WU    53248u    // 512
#define OFF_WM    53760u    // 512
#define OFF_B1B   54272u    // 256
#define OFF_B2B   54528u    // 128
#define OFF_WR    54656u    // 96
#define OFF_SC    54752u    // 16
#define SMEM_BYTES 54784

__device__ uint2 gB1[6 * 8 * 32];   // W1 B-fragments [kt][nt][lane]
__device__ uint2 gB2[4 * 4 * 32];   // W2 B-fragments [kt][nt][lane]
__device__ uint2 gB3[2 * 2 * 32];   // W3 B-fragments [kt][nt][lane]
__device__ u32   gU[NU * 32];       // per-user 128B row: 16 u32 bf16-pairs + wideW + pad
__device__ u32   gM[NM * 32];       // per-movie row, same layout

// ---------------- helpers ----------------
__device__ __forceinline__ u32 pkbf(float lo, float hi) {
    u32 r; asm("cvt.rn.bf16x2.f32 %0,%1,%2;" : "=r"(r) : "f"(hi), "f"(lo)); return r;
}
__device__ __forceinline__ u32 smem_u32(const void* p) {
    u32 a; asm("{ .reg .u64 t; cvta.to.shared.u64 t, %1; cvt.u32.u64 %0, t; }" : "=r"(a) : "l"(p));
    return a;
}
__device__ __forceinline__ void mma16816(float* c, const u32* a, u32 b0, u32 b1) {
    asm("mma.sync.aligned.m16n8k16.row.col.f32.bf16.bf16.f32 "
        "{%0,%1,%2,%3},{%4,%5,%6,%7},{%8,%9},{%0,%1,%2,%3};"
        : "+f"(c[0]), "+f"(c[1]), "+f"(c[2]), "+f"(c[3])
        : "r"(a[0]), "r"(a[1]), "r"(a[2]), "r"(a[3]), "r"(b0), "r"(b1));
}
__device__ __forceinline__ void ldmA(u32* a, u32 saddr) {
    asm volatile("ldmatrix.sync.aligned.m8n8.x4.shared.b16 {%0,%1,%2,%3}, [%4];"
                 : "=r"(a[0]), "=r"(a[1]), "=r"(a[2]), "=r"(a[3]) : "r"(saddr));
}
__device__ __forceinline__ float relu(float x) { return fmaxf(x, 0.f); }

// ---------------- prep: weight fragments + fused bf16 gather tables ----------------
__global__ void prep_kernel(const float* __restrict__ W1, const float* __restrict__ W2,
                            const float* __restrict__ W3,
                            const float* __restrict__ utab, const float* __restrict__ mtab,
                            const float* __restrict__ wideW) {
    int i = blockIdx.x * blockDim.x + threadIdx.x;
    int stride = gridDim.x * blockDim.x;
    for (int idx = i; idx < 6 * 8 * 32; idx += stride) {
        int lane = idx & 31, nt = (idx >> 5) & 7, kt = idx >> 8;
        int g = lane >> 2, t = lane & 3;
        int n = nt * 8 + g;
        int k0 = kt * 16 + t * 2;
        float v0 = (k0     < 85) ? W1[(k0    ) * 64 + n] : 0.f;
        float v1 = (k0 + 1 < 85) ? W1[(k0 + 1) * 64 + n] : 0.f;
        float v2 = (k0 + 8 < 85) ? W1[(k0 + 8) * 64 + n] : 0.f;
        float v3 = (k0 + 9 < 85) ? W1[(k0 + 9) * 64 + n] : 0.f;
        gB1[idx] = make_uint2(pkbf(v0, v1), pkbf(v2, v3));
    }
    for (int idx = i; idx < 4 * 4 * 32; idx += stride) {
        int lane = idx & 31, nt = (idx >> 5) & 3, kt = idx >> 7;
        int g = lane >> 2, t = lane & 3;
        int n = nt * 8 + g;
        int k0 = kt * 16 + t * 2;
        gB2[idx] = make_uint2(pkbf(W2[k0 * 32 + n],       W2[(k0 + 1) * 32 + n]),
                              pkbf(W2[(k0 + 8) * 32 + n], W2[(k0 + 9) * 32 + n]));
    }
    for (int idx = i; idx < 2 * 2 * 32; idx += stride) {
        int lane = idx & 31, nt = (idx >> 5) & 1, kt = idx >> 6;
        int g = lane >> 2, t = lane & 3;
        int n = nt * 8 + g;
        int k0 = kt * 16 + t * 2;
        gB3[idx] = make_uint2(pkbf(W3[k0 * 16 + n],       W3[(k0 + 1) * 16 + n]),
                              pkbf(W3[(k0 + 8) * 16 + n], W3[(k0 + 9) * 16 + n]));
    }
    for (int id = i; id < NU; id += stride) {
        u32* row = gU + id * 32;
        const float* e = utab + id * 32;
        #pragma unroll
        for (int j = 0; j < 16; j++) row[j] = pkbf(e[2*j], e[2*j + 1]);
        row[16] = __float_as_uint(wideW[id]);
        #pragma unroll
        for (int j = 17; j < 32; j++) row[j] = 0u;
    }
    for (int id = i; id < NM; id += stride) {
        u32* row = gM + id * 32;
        const float* e = mtab + id * 32;
        #pragma unroll
        for (int j = 0; j < 16; j++) row[j] = pkbf(e[2*j], e[2*j + 1]);
        row[16] = __float_as_uint(wideW[NU + id]);
        #pragma unroll
        for (int j = 17; j < 32; j++) row[j] = 0u;
    }
}

// ---------------- main kernel ----------------
__global__ void __launch_bounds__(THREADS, 4)
wd_mma(const int* __restrict__ uids, const int* __restrict__ mids,
       const float* __restrict__ gender, const float* __restrict__ age,
       const float* __restrict__ occ, const float* __restrict__ genres,
       const float* __restrict__ wideW, const float* __restrict__ wideB,
       const float* __restrict__ b1, const float* __restrict__ b2,
       const float* __restrict__ b3, const float* __restrict__ W4,
       const float* __restrict__ b4, float* __restrict__ out)
{
    extern __shared__ __align__(16) char smem[];
    u32*   sA1w  = (u32*)(smem + OFF_A1);
    uint2* sB1f  = (uint2*)(smem + OFF_B1F);
    uint2* sB2f  = (uint2*)(smem + OFF_B2F);
    float* sG    = (float*)(smem + OFF_G);
    int*   sIds  = (int*)(smem + OFF_IDS);
    float* sWU   = (float*)(smem + OFF_WU);
    float* sWM   = (float*)(smem + OFF_WM);
    float* sB1b  = (float*)(smem + OFF_B1B);
    float* sB2b  = (float*)(smem + OFF_B2B);
    float* sWr   = (float*)(smem + OFF_WR);
    float* sSc   = (float*)(smem + OFF_SC);

    const int tid  = threadIdx.x;
    const int wid  = tid >> 5;
    const int lane = tid & 31;
    const int g    = lane >> 2;
    const int t4   = lane & 3;

    // ---- one-time staging ----
    for (int i = tid; i < 6 * 8 * 32; i += THREADS) sB1f[i] = gB1[i];
    for (int i = tid; i < 4 * 4 * 32; i += THREADS) sB2f[i] = gB2[i];
    if (tid < 64) sB1b[tid] = b1[tid];
    if (tid < 32) sB2b[tid] = b2[tid];
    if (tid < 21) sWr[tid]  = wideW[NU + NM + tid];
    if (tid == 0) { sSc[0] = b4[0]; sSc[1] = wideB[0]; }

    // register-resident layer-3 fragments + per-lane tail constants
    uint2 rB3[2][2];
    #pragma unroll
    for (int kt = 0; kt < 2; kt++)
        #pragma unroll
        for (int nt = 0; nt < 2; nt++)
            rB3[kt][nt] = gB3[(kt * 2 + nt) * 32 + lane];
    const int c0 = 2 * t4;
    const float b3c0 = b3[c0], b3c1 = b3[c0 + 1], b3c2 = b3[8 + c0], b3c3 = b3[9 + c0];
    const float w4c0 = W4[c0], w4c1 = W4[c0 + 1], w4c2 = W4[8 + c0], w4c3 = W4[9 + c0];
    __syncthreads();

    u32*   myA   = sA1w + wid * (32 * AW);
    float* myG   = sG + wid * 576;
    int*   myIds = sIds + wid * 64;
    float* myWU  = sWU + wid * 32;
    float* myWM  = sWM + wid * 32;

    // per-lane ldmatrix address (mtile 0, kt 0)
    const u32 aBase = smem_u32(myA);
    const u32 aAddr = aBase + (u32)(((lane & 15) * AW + (lane >> 4) * 4) * 4);

    for (int tile = blockIdx.x; tile < NTILES; tile += gridDim.x) {
        const int R = tile * 128 + wid * 32;
        __syncwarp();

        // ---- genres (coalesced stream) + ids ----
        {
            const float2* gb = (const float2*)(genres + (size_t)R * 18);
            float2* mg = (float2*)myG;
            #pragma unroll
            for (int j = 0; j < 9; j++) mg[lane + 32 * j] = gb[lane + 32 * j];
            myIds[lane]      = uids[R + lane];
            myIds[32 + lane] = mids[R + lane];
        }
        __syncwarp();

        // ---- fused gather: bf16 emb (pre-converted) + wide scalar (same 128B line) ----
        {
            const int ch = lane & 3;     // 16B chunk within 64B emb
            const int r8 = lane >> 2;    // 8 rows per pass
            #pragma unroll
            for (int p = 0; p < 4; p++) {
                const int row = r8 + 8 * p;
                const u32* ub = gU + (u32)myIds[row] * 32;
                const u32* mb = gM + (u32)myIds[32 + row] * 32;
                uint4 vu = ((const uint4*)ub)[ch];
                uint4 vm = ((const uint4*)mb)[ch];
                u32* rb = myA + row * AW;
                *(uint4*)(rb + 4 * ch)      = vu;
                *(uint4*)(rb + 16 + 4 * ch) = vm;
                if (ch == 0) {
                    myWU[row] = __uint_as_float(ub[16]);
                    myWM[row] = __uint_as_float(mb[16]);
                }
            }
        }
        __syncwarp();

        // ---- rest features + wide path (full warp, one row per lane) ----
        float wide;
        {
            const int r = R + lane;
            float fv[21];
            fv[0] = gender[r]; fv[1] = age[r]; fv[2] = occ[r];
            #pragma unroll
            for (int q = 0; q < 9; q++) {
                float2 p = *(const float2*)(myG + lane * 18 + 2 * q);
                fv[3 + 2 * q] = p.x; fv[4 + 2 * q] = p.y;
            }
            wide = sSc[1] + myWU[lane] + myWM[lane];
            #pragma unroll
            for (int i = 0; i < 21; i++) wide = fmaf(fv[i], sWr[i], wide);

            u32 w[16];
            #pragma unroll
            for (int j = 0; j < 10; j++) w[j] = pkbf(fv[2 * j], fv[2 * j + 1]);
            w[10] = pkbf(fv[20], 0.f);
            w[11] = w[12] = w[13] = w[14] = w[15] = 0u;
            u32* rb = myA + lane * AW + 32;
            #pragma unroll
            for (int j = 0; j < 4; j++)
                *(uint4*)(rb + j * 4) = make_uint4(w[4*j], w[4*j+1], w[4*j+2], w[4*j+3]);
        }
        __syncwarp();

        // ---- layer 1: two 16-row m-tiles share each B fragment ----
        float acc[2][8][4];
        #pragma unroll
        for (int m = 0; m < 2; m++)
            #pragma unroll
            for (int nt = 0; nt < 8; nt++)
                acc[m][nt][0] = acc[m][nt][1] = acc[m][nt][2] = acc[m][nt][3] = 0.f;
        #pragma unroll
        for (int kt = 0; kt < 6; kt++) {
            u32 a0[4], a1[4];
            ldmA(a0, aAddr + kt * 32u);
            ldmA(a1, aAddr + 16u * AW * 4u + kt * 32u);
            #pragma unroll
            for (int nt = 0; nt < 8; nt++) {
                uint2 b = sB1f[(kt * 8 + nt) * 32 + lane];
                mma16816(acc[0][nt], a0, b.x, b.y);
                mma16816(acc[1][nt], a1, b.x, b.y);
            }
        }

        // ---- epilogue 1: bias+relu -> layer-2 A-frags (registers) ----
        u32 a2f[2][4][4];
        #pragma unroll
        for (int m = 0; m < 2; m++)
            #pragma unroll
            for (int kt = 0; kt < 4; kt++) {
                int j0 = 2 * kt, j1 = j0 + 1;
                float2 bb0 = *(const float2*)(sB1b + j0 * 8 + t4 * 2);
                float2 bb1 = *(const float2*)(sB1b + j1 * 8 + t4 * 2);
                a2f[m][kt][0] = pkbf(relu(acc[m][j0][0] + bb0.x), relu(acc[m][j0][1] + bb0.y));
                a2f[m][kt][1] = pkbf(relu(acc[m][j0][2] + bb0.x), relu(acc[m][j0][3] + bb0.y));
                a2f[m][kt][2] = pkbf(relu(acc[m][j1][0] + bb1.x), relu(acc[m][j1][1] + bb1.y));
                a2f[m][kt][3] = pkbf(relu(acc[m][j1][2] + bb1.x), relu(acc[m][j1][3] + bb1.y));
            }

        // ---- layer 2 ----
        float acc2[2][4][4];
        #pragma unroll
        for (int m = 0; m < 2; m++)
            #pragma unroll
            for (int nt = 0; nt < 4; nt++)
                acc2[m][nt][0] = acc2[m][nt][1] = acc2[m][nt][2] = acc2[m][nt][3] = 0.f;
        #pragma unroll
        for (int kt = 0; kt < 4; kt++)
            #pragma unroll
            for (int nt = 0; nt < 4; nt++) {
                uint2 b = sB2f[(kt * 4 + nt) * 32 + lane];
                mma16816(acc2[0][nt], a2f[0][kt], b.x, b.y);
                mma16816(acc2[1][nt], a2f[1][kt], b.x, b.y);
            }

        // ---- epilogue 2 + layer 3 (register B) + tail, per m-tile ----
        #pragma unroll
        for (int m = 0; m < 2; m++) {
            u32 a3f[2][4];
            #pragma unroll
            for (int kt = 0; kt < 2; kt++) {
                int j0 = 2 * kt, j1 = j0 + 1;
                float2 bb0 = *(const float2*)(sB2b + j0 * 8 + t4 * 2);
                float2 bb1 = *(const float2*)(sB2b + j1 * 8 + t4 * 2);
                a3f[kt][0] = pkbf(relu(acc2[m][j0][0] + bb0.x), relu(acc2[m][j0][1] + bb0.y));
                a3f[kt][1] = pkbf(relu(acc2[m][j0][2] + bb0.x), relu(acc2[m][j0][3] + bb0.y));
                a3f[kt][2] = pkbf(relu(acc2[m][j1][0] + bb1.x), relu(acc2[m][j1][1] + bb1.y));
                a3f[kt][3] = pkbf(relu(acc2[m][j1][2] + bb1.x), relu(acc2[m][j1][3] + bb1.y));
            }
            float acc3[2][4];
            #pragma unroll
            for (int nt = 0; nt < 2; nt++)
                acc3[nt][0] = acc3[nt][1] = acc3[nt][2] = acc3[nt][3] = 0.f;
            #pragma unroll
            for (int kt = 0; kt < 2; kt++)
                #pragma unroll
                for (int nt = 0; nt < 2; nt++)
                    mma16816(acc3[nt], a3f[kt], rB3[kt][nt].x, rB3[kt][nt].y);

            float dpg, dph;
            dpg  = relu(acc3[0][0] + b3c0) * w4c0;
            dpg  = fmaf(relu(acc3[0][1] + b3c1), w4c1, dpg);
            dpg  = fmaf(relu(acc3[1][0] + b3c2), w4c2, dpg);
            dpg  = fmaf(relu(acc3[1][1] + b3c3), w4c3, dpg);
            dph  = relu(acc3[0][2] + b3c0) * w4c0;
            dph  = fmaf(relu(acc3[0][3] + b3c1), w4c1, dph);
            dph  = fmaf(relu(acc3[1][2] + b3c2), w4c2, dph);
            dph  = fmaf(relu(acc3[1][3] + b3c3), w4c3, dph);
            dpg += __shfl_xor_sync(0xffffffffu, dpg, 1);
            dpg += __shfl_xor_sync(0xffffffffu, dpg, 2);
            dph += __shfl_xor_sync(0xffffffffu, dph, 1);
            dph += __shfl_xor_sync(0xffffffffu, dph, 2);

            float wg = __shfl_sync(0xffffffffu, wide, m * 16 + g);
            float wh = __shfl_sync(0xffffffffu, wide, m * 16 + 8 + g);
            if (t4 == 0) {
                float zg = wg + dpg + sSc[0];
                float zh = wh + dph + sSc[0];
                out[R + m * 16 + g]     = 1.f / (1.f + expf(-zg));
                out[R + m * 16 + 8 + g] = 1.f / (1.f + expf(-zh));
            }
        }
    }
}

extern "C" void kernel_launch(void* const* d_in, const int* in_sizes, int n_in,
                              void* d_out, int out_size) {
    const int*   uids   = (const int*)  d_in[0];
    const int*   mids   = (const int*)  d_in[1];
    const float* gender = (const float*)d_in[2];
    const float* age    = (const float*)d_in[3];
    const float* occ    = (const float*)d_in[4];
    const float* genres = (const float*)d_in[5];
    const float* wideW  = (const float*)d_in[6];
    const float* wideB  = (const float*)d_in[7];
    const float* utab   = (const float*)d_in[8];
    const float* mtab   = (const float*)d_in[9];
    const float* W1     = (const float*)d_in[10];
    const float* b1     = (const float*)d_in[11];
    const float* W2     = (const float*)d_in[12];
    const float* b2     = (const float*)d_in[13];
    const float* W3     = (const float*)d_in[14];
    const float* b3     = (const float*)d_in[15];
    const float* W4     = (const float*)d_in[16];
    const float* b4     = (const float*)d_in[17];
    float* out = (float*)d_out;

    static int inited = 0;
    if (!inited) {
        cudaFuncSetAttribute(wd_mma, cudaFuncAttributeMaxDynamicSharedMemorySize, SMEM_BYTES);
        inited = 1;
    }

    prep_kernel<<<64, 256>>>(W1, W2, W3, utab, mtab, wideW);
    wd_mma<<<GRID, THREADS, SMEM_BYTES>>>(uids, mids, gender, age, occ, genres,
                                          wideW, wideB, b1, b2, b3, W4, b4, out);
}

// round 12
// speedup vs baseline: 1.1686x; 1.1686x over previous
#include <cuda_runtime.h>
#include <cuda_bf16.h>
#include <stdint.h>

#define NU 6041
#define NM 3953
#define B_TOTAL 1048576
#define NTILES 8192          // 128 rows per CTA-tile
#define GRID 592
#define THREADS 128          // 4 warps, 32 rows/warp
#define AW 52                // u32 words per A row

typedef unsigned long long u64;
typedef unsigned int u32;

// ---- dynamic smem offsets (bytes) ----
#define OFF_A1    0u        // 4*32*52*4 = 26624
#define OFF_B1F   26624u    // 12288 (uint4 packed: 6kt * 4ntp * 32)
#define OFF_B2F   38912u    // 4096  (uint4 packed: 4kt * 2ntp * 32)
#define OFF_G     43008u    // 4*576*4 = 9216
#define OFF_IDS   52224u    // 4*64*4 = 1024
#define OFF_WU    53248u    // 512
#define OFF_WM    53760u    // 512
#define OFF_B1B   54272u    // 256
#define OFF_B2B   54528u    // 128
#define OFF_WR    54656u    // 96
#define OFF_SC    54752u    // 16
#define SMEM_BYTES 54784

__device__ uint4 gB1p[6 * 4 * 32];  // W1 B-fragments packed [kt][ntp][lane]
__device__ uint4 gB2p[4 * 2 * 32];  // W2 B-fragments packed [kt][ntp][lane]
__device__ uint2 gB3[2 * 2 * 32];   // W3 B-fragments [kt][nt][lane]
__device__ u32   gU[NU * 32];       // per-user 128B row: 16 u32 bf16-pairs + wideW (words 17+ unused)
__device__ u32   gM[NM * 32];       // per-movie row, same layout

// ---------------- helpers ----------------
__device__ __forceinline__ u32 pkbf(float lo, float hi) {
    u32 r; asm("cvt.rn.bf16x2.f32 %0,%1,%2;" : "=r"(r) : "f"(hi), "f"(lo)); return r;
}
__device__ __forceinline__ u32 smem_u32(const void* p) {
    u32 a; asm("{ .reg .u64 t; cvta.to.shared.u64 t, %1; cvt.u32.u64 %0, t; }" : "=r"(a) : "l"(p));
    return a;
}
__device__ __forceinline__ void mma16816(float* c, const u32* a, u32 b0, u32 b1) {
    asm("mma.sync.aligned.m16n8k16.row.col.f32.bf16.bf16.f32 "
        "{%0,%1,%2,%3},{%4,%5,%6,%7},{%8,%9},{%0,%1,%2,%3};"
        : "+f"(c[0]), "+f"(c[1]), "+f"(c[2]), "+f"(c[3])
        : "r"(a[0]), "r"(a[1]), "r"(a[2]), "r"(a[3]), "r"(b0), "r"(b1));
}
__device__ __forceinline__ void ldmA(u32* a, u32 saddr) {
    asm volatile("ldmatrix.sync.aligned.m8n8.x4.shared.b16 {%0,%1,%2,%3}, [%4];"
                 : "=r"(a[0]), "=r"(a[1]), "=r"(a[2]), "=r"(a[3]) : "r"(saddr));
}
__device__ __forceinline__ float relu(float x) { return fmaxf(x, 0.f); }

// ---------------- prep: weight fragments + fused bf16 gather tables ----------------
__global__ void prep_kernel(const float* __restrict__ W1, const float* __restrict__ W2,
                            const float* __restrict__ W3,
                            const float* __restrict__ utab, const float* __restrict__ mtab,
                            const float* __restrict__ wideW) {
    int i = blockIdx.x * blockDim.x + threadIdx.x;
    int stride = gridDim.x * blockDim.x;

    // W1 packed fragments: two n-tiles per uint4
    for (int idx = i; idx < 6 * 4 * 32; idx += stride) {
        int lane = idx & 31, ntp = (idx >> 5) & 3, kt = idx >> 7;
        int g = lane >> 2, t = lane & 3;
        int n0 = ntp * 16 + g, n1 = n0 + 8;
        int k0 = kt * 16 + t * 2;
        float a0 = (k0     < 85) ? W1[(k0    ) * 64 + n0] : 0.f;
        float a1 = (k0 + 1 < 85) ? W1[(k0 + 1) * 64 + n0] : 0.f;
        float a2 = (k0 + 8 < 85) ? W1[(k0 + 8) * 64 + n0] : 0.f;
        float a3 = (k0 + 9 < 85) ? W1[(k0 + 9) * 64 + n0] : 0.f;
        float c0 = (k0     < 85) ? W1[(k0    ) * 64 + n1] : 0.f;
        float c1 = (k0 + 1 < 85) ? W1[(k0 + 1) * 64 + n1] : 0.f;
        float c2 = (k0 + 8 < 85) ? W1[(k0 + 8) * 64 + n1] : 0.f;
        float c3 = (k0 + 9 < 85) ? W1[(k0 + 9) * 64 + n1] : 0.f;
        gB1p[idx] = make_uint4(pkbf(a0, a1), pkbf(a2, a3), pkbf(c0, c1), pkbf(c2, c3));
    }
    // W2 packed fragments
    for (int idx = i; idx < 4 * 2 * 32; idx += stride) {
        int lane = idx & 31, ntp = (idx >> 5) & 1, kt = idx >> 6;
        int g = lane >> 2, t = lane & 3;
        int n0 = ntp * 16 + g, n1 = n0 + 8;
        int k0 = kt * 16 + t * 2;
        gB2p[idx] = make_uint4(
            pkbf(W2[k0 * 32 + n0],       W2[(k0 + 1) * 32 + n0]),
            pkbf(W2[(k0 + 8) * 32 + n0], W2[(k0 + 9) * 32 + n0]),
            pkbf(W2[k0 * 32 + n1],       W2[(k0 + 1) * 32 + n1]),
            pkbf(W2[(k0 + 8) * 32 + n1], W2[(k0 + 9) * 32 + n1]));
    }
    // W3 fragments
    for (int idx = i; idx < 2 * 2 * 32; idx += stride) {
        int lane = idx & 31, nt = (idx >> 5) & 1, kt = idx >> 6;
        int g = lane >> 2, t = lane & 3;
        int n = nt * 8 + g;
        int k0 = kt * 16 + t * 2;
        gB3[idx] = make_uint2(pkbf(W3[k0 * 16 + n],       W3[(k0 + 1) * 16 + n]),
                              pkbf(W3[(k0 + 8) * 16 + n], W3[(k0 + 9) * 16 + n]));
    }
    // fused gather tables: chunk-parallel (4 uint4 emb chunks per id)
    for (int idx = i; idx < NU * 4; idx += stride) {
        int id = idx >> 2, j = idx & 3;
        const float* e = utab + id * 32 + j * 8;
        ((uint4*)(gU + id * 32))[j] = make_uint4(pkbf(e[0], e[1]), pkbf(e[2], e[3]),
                                                 pkbf(e[4], e[5]), pkbf(e[6], e[7]));
    }
    for (int idx = i; idx < NM * 4; idx += stride) {
        int id = idx >> 2, j = idx & 3;
        const float* e = mtab + id * 32 + j * 8;
        ((uint4*)(gM + id * 32))[j] = make_uint4(pkbf(e[0], e[1]), pkbf(e[2], e[3]),
                                                 pkbf(e[4], e[5]), pkbf(e[6], e[7]));
    }
    for (int id = i; id < NU; id += stride) gU[id * 32 + 16] = __float_as_uint(wideW[id]);
    for (int id = i; id < NM; id += stride) gM[id * 32 + 16] = __float_as_uint(wideW[NU + id]);
}

// ---------------- main kernel ----------------
__global__ void __launch_bounds__(THREADS, 4)
wd_mma(const int* __restrict__ uids, const int* __restrict__ mids,
       const float* __restrict__ gender, const float* __restrict__ age,
       const float* __restrict__ occ, const float* __restrict__ genres,
       const float* __restrict__ wideW, const float* __restrict__ wideB,
       const float* __restrict__ b1, const float* __restrict__ b2,
       const float* __restrict__ b3, const float* __restrict__ W4,
       const float* __restrict__ b4, float* __restrict__ out)
{
    extern __shared__ __align__(16) char smem[];
    u32*   sA1w  = (u32*)(smem + OFF_A1);
    uint4* sB1p  = (uint4*)(smem + OFF_B1F);
    uint4* sB2p  = (uint4*)(smem + OFF_B2F);
    float* sG    = (float*)(smem + OFF_G);
    int*   sIds  = (int*)(smem + OFF_IDS);
    float* sWU   = (float*)(smem + OFF_WU);
    float* sWM   = (float*)(smem + OFF_WM);
    float* sB1b  = (float*)(smem + OFF_B1B);
    float* sB2b  = (float*)(smem + OFF_B2B);
    float* sWr   = (float*)(smem + OFF_WR);
    float* sSc   = (float*)(smem + OFF_SC);

    const int tid  = threadIdx.x;
    const int wid  = tid >> 5;
    const int lane = tid & 31;
    const int g    = lane >> 2;
    const int t4   = lane & 3;

    // ---- one-time staging ----
    for (int i = tid; i < 6 * 4 * 32; i += THREADS) sB1p[i] = gB1p[i];
    for (int i = tid; i < 4 * 2 * 32; i += THREADS) sB2p[i] = gB2p[i];
    if (tid < 64) sB1b[tid] = b1[tid];
    if (tid < 32) sB2b[tid] = b2[tid];
    if (tid < 21) sWr[tid]  = wideW[NU + NM + tid];
    if (tid == 0) { sSc[0] = b4[0]; sSc[1] = wideB[0]; }

    uint2 rB3[2][2];
    #pragma unroll
    for (int kt = 0; kt < 2; kt++)
        #pragma unroll
        for (int nt = 0; nt < 2; nt++)
            rB3[kt][nt] = gB3[(kt * 2 + nt) * 32 + lane];
    const int c0 = 2 * t4;
    const float b3c0 = b3[c0], b3c1 = b3[c0 + 1], b3c2 = b3[8 + c0], b3c3 = b3[9 + c0];
    const float w4c0 = W4[c0], w4c1 = W4[c0 + 1], w4c2 = W4[8 + c0], w4c3 = W4[9 + c0];
    __syncthreads();

    u32*   myA   = sA1w + wid * (32 * AW);
    float* myG   = sG + wid * 576;
    int*   myIds = sIds + wid * 64;
    float* myWU  = sWU + wid * 32;
    float* myWM  = sWM + wid * 32;

    const u32 aBase = smem_u32(myA);
    const u32 aAddr = aBase + (u32)(((lane & 15) * AW + (lane >> 4) * 4) * 4);

    // ---- prefetch first tile's ids ----
    int pu = 0, pm = 0;
    if (blockIdx.x < NTILES) {
        pu = uids[blockIdx.x * 128 + wid * 32 + lane];
        pm = mids[blockIdx.x * 128 + wid * 32 + lane];
    }

    for (int tile = blockIdx.x; tile < NTILES; tile += gridDim.x) {
        const int R = tile * 128 + wid * 32;
        __syncwarp();

        // ---- genres (coalesced stream) + prefetched ids -> smem ----
        {
            const float2* gb = (const float2*)(genres + (size_t)R * 18);
            float2* mg = (float2*)myG;
            #pragma unroll
            for (int j = 0; j < 9; j++) mg[lane + 32 * j] = gb[lane + 32 * j];
            myIds[lane]      = pu;
            myIds[32 + lane] = pm;
        }
        __syncwarp();

        // ---- fused gather: bf16 emb + wide scalar (same 128B line) ----
        {
            const int ch = lane & 3;
            const int r8 = lane >> 2;
            #pragma unroll
            for (int p = 0; p < 4; p++) {
                const int row = r8 + 8 * p;
                const u32* ub = gU + (u32)myIds[row] * 32;
                const u32* mb = gM + (u32)myIds[32 + row] * 32;
                uint4 vu = ((const uint4*)ub)[ch];
                uint4 vm = ((const uint4*)mb)[ch];
                u32* rb = myA + row * AW;
                *(uint4*)(rb + 4 * ch)      = vu;
                *(uint4*)(rb + 16 + 4 * ch) = vm;
                if (ch == 0) {
                    myWU[row] = __uint_as_float(ub[16]);
                    myWM[row] = __uint_as_float(mb[16]);
                }
            }
        }
        __syncwarp();

        // ---- rest features + wide path (one row per lane) ----
        float wide;
        {
            const int r = R + lane;
            float fv[21];
            fv[0] = gender[r]; fv[1] = age[r]; fv[2] = occ[r];
            #pragma unroll
            for (int q = 0; q < 9; q++) {
                float2 p = *(const float2*)(myG + lane * 18 + 2 * q);
                fv[3 + 2 * q] = p.x; fv[4 + 2 * q] = p.y;
            }
            wide = sSc[1] + myWU[lane] + myWM[lane];
            #pragma unroll
            for (int i = 0; i < 21; i++) wide = fmaf(fv[i], sWr[i], wide);

            u32 w[16];
            #pragma unroll
            for (int j = 0; j < 10; j++) w[j] = pkbf(fv[2 * j], fv[2 * j + 1]);
            w[10] = pkbf(fv[20], 0.f);
            w[11] = w[12] = w[13] = w[14] = w[15] = 0u;
            u32* rb = myA + lane * AW + 32;
            #pragma unroll
            for (int j = 0; j < 4; j++)
                *(uint4*)(rb + j * 4) = make_uint4(w[4*j], w[4*j+1], w[4*j+2], w[4*j+3]);
        }
        __syncwarp();

        // ---- prefetch NEXT tile's ids (hidden under MMA section) ----
        {
            int nt2 = tile + gridDim.x;
            if (nt2 < NTILES) {
                pu = uids[nt2 * 128 + wid * 32 + lane];
                pm = mids[nt2 * 128 + wid * 32 + lane];
            }
        }

        // ---- layer 1: two 16-row m-tiles share each packed B fragment ----
        float acc[2][8][4];
        #pragma unroll
        for (int m = 0; m < 2; m++)
            #pragma unroll
            for (int nt = 0; nt < 8; nt++)
                acc[m][nt][0] = acc[m][nt][1] = acc[m][nt][2] = acc[m][nt][3] = 0.f;
        #pragma unroll
        for (int kt = 0; kt < 6; kt++) {
            u32 a0[4], a1[4];
            ldmA(a0, aAddr + kt * 32u);
            ldmA(a1, aAddr + 16u * AW * 4u + kt * 32u);
            #pragma unroll
            for (int ntp = 0; ntp < 4; ntp++) {
                uint4 q = sB1p[(kt * 4 + ntp) * 32 + lane];
                mma16816(acc[0][2*ntp],     a0, q.x, q.y);
                mma16816(acc[0][2*ntp + 1], a0, q.z, q.w);
                mma16816(acc[1][2*ntp],     a1, q.x, q.y);
                mma16816(acc[1][2*ntp + 1], a1, q.z, q.w);
            }
        }

        // ---- epilogue 1: bias+relu -> layer-2 A-frags ----
        u32 a2f[2][4][4];
        #pragma unroll
        for (int m = 0; m < 2; m++)
            #pragma unroll
            for (int kt = 0; kt < 4; kt++) {
                int j0 = 2 * kt, j1 = j0 + 1;
                float2 bb0 = *(const float2*)(sB1b + j0 * 8 + t4 * 2);
                float2 bb1 = *(const float2*)(sB1b + j1 * 8 + t4 * 2);
                a2f[m][kt][0] = pkbf(relu(acc[m][j0][0] + bb0.x), relu(acc[m][j0][1] + bb0.y));
                a2f[m][kt][1] = pkbf(relu(acc[m][j0][2] + bb0.x), relu(acc[m][j0][3] + bb0.y));
                a2f[m][kt][2] = pkbf(relu(acc[m][j1][0] + bb1.x), relu(acc[m][j1][1] + bb1.y));
                a2f[m][kt][3] = pkbf(relu(acc[m][j1][2] + bb1.x), relu(acc[m][j1][3] + bb1.y));
            }

        // ---- layer 2 ----
        float acc2[2][4][4];
        #pragma unroll
        for (int m = 0; m < 2; m++)
            #pragma unroll
            for (int nt = 0; nt < 4; nt++)
                acc2[m][nt][0] = acc2[m][nt][1] = acc2[m][nt][2] = acc2[m][nt][3] = 0.f;
        #pragma unroll
        for (int kt = 0; kt < 4; kt++)
            #pragma unroll
            for (int ntp = 0; ntp < 2; ntp++) {
                uint4 q = sB2p[(kt * 2 + ntp) * 32 + lane];
                mma16816(acc2[0][2*ntp],     a2f[0][kt], q.x, q.y);
                mma16816(acc2[0][2*ntp + 1], a2f[0][kt], q.z, q.w);
                mma16816(acc2[1][2*ntp],     a2f[1][kt], q.x, q.y);
                mma16816(acc2[1][2*ntp + 1], a2f[1][kt], q.z, q.w);
            }

        // ---- epilogue 2 + layer 3 + tail, per m-tile ----
        #pragma unroll
        for (int m = 0; m < 2; m++) {
            u32 a3f[2][4];
            #pragma unroll
            for (int kt = 0; kt < 2; kt++) {
                int j0 = 2 * kt, j1 = j0 + 1;
                float2 bb0 = *(const float2*)(sB2b + j0 * 8 + t4 * 2);
                float2 bb1 = *(const float2*)(sB2b + j1 * 8 + t4 * 2);
                a3f[kt][0] = pkbf(relu(acc2[m][j0][0] + bb0.x), relu(acc2[m][j0][1] + bb0.y));
                a3f[kt][1] = pkbf(relu(acc2[m][j0][2] + bb0.x), relu(acc2[m][j0][3] + bb0.y));
                a3f[kt][2] = pkbf(relu(acc2[m][j1][0] + bb1.x), relu(acc2[m][j1][1] + bb1.y));
                a3f[kt][3] = pkbf(relu(acc2[m][j1][2] + bb1.x), relu(acc2[m][j1][3] + bb1.y));
            }
            float acc3[2][4];
            #pragma unroll
            for (int nt = 0; nt < 2; nt++)
                acc3[nt][0] = acc3[nt][1] = acc3[nt][2] = acc3[nt][3] = 0.f;
            #pragma unroll
            for (int kt = 0; kt < 2; kt++)
                #pragma unroll
                for (int nt = 0; nt < 2; nt++)
                    mma16816(acc3[nt], a3f[kt], rB3[kt][nt].x, rB3[kt][nt].y);

            float dpg, dph;
            dpg  = relu(acc3[0][0] + b3c0) * w4c0;
            dpg  = fmaf(relu(acc3[0][1] + b3c1), w4c1, dpg);
            dpg  = fmaf(relu(acc3[1][0] + b3c2), w4c2, dpg);
            dpg  = fmaf(relu(acc3[1][1] + b3c3), w4c3, dpg);
            dph  = relu(acc3[0][2] + b3c0) * w4c0;
            dph  = fmaf(relu(acc3[0][3] + b3c1), w4c1, dph);
            dph  = fmaf(relu(acc3[1][2] + b3c2), w4c2, dph);
            dph  = fmaf(relu(acc3[1][3] + b3c3), w4c3, dph);
            dpg += __shfl_xor_sync(0xffffffffu, dpg, 1);
            dpg += __shfl_xor_sync(0xffffffffu, dpg, 2);
            dph += __shfl_xor_sync(0xffffffffu, dph, 1);
            dph += __shfl_xor_sync(0xffffffffu, dph, 2);

            float wg = __shfl_sync(0xffffffffu, wide, m * 16 + g);
            float wh = __shfl_sync(0xffffffffu, wide, m * 16 + 8 + g);
            if (t4 == 0) {
                float zg = wg + dpg + sSc[0];
                float zh = wh + dph + sSc[0];
                out[R + m * 16 + g]     = 1.f / (1.f + expf(-zg));
                out[R + m * 16 + 8 + g] = 1.f / (1.f + expf(-zh));
            }
        }
    }
}

extern "C" void kernel_launch(void* const* d_in, const int* in_sizes, int n_in,
                              void* d_out, int out_size) {
    const int*   uids   = (const int*)  d_in[0];
    const int*   mids   = (const int*)  d_in[1];
    const float* gender = (const float*)d_in[2];
    const float* age    = (const float*)d_in[3];
    const float* occ    = (const float*)d_in[4];
    const float* genres = (const float*)d_in[5];
    const float* wideW  = (const float*)d_in[6];
    const float* wideB  = (const float*)d_in[7];
    const float* utab   = (const float*)d_in[8];
    const float* mtab   = (const float*)d_in[9];
    const float* W1     = (const float*)d_in[10];
    const float* b1     = (const float*)d_in[11];
    const float* W2     = (const float*)d_in[12];
    const float* b2     = (const float*)d_in[13];
    const float* W3     = (const float*)d_in[14];
    const float* b3     = (const float*)d_in[15];
    const float* W4     = (const float*)d_in[16];
    const float* b4     = (const float*)d_in[17];
    float* out = (float*)d_out;

    static int inited = 0;
    if (!inited) {
        cudaFuncSetAttribute(wd_mma, cudaFuncAttributeMaxDynamicSharedMemorySize, SMEM_BYTES);
        inited = 1;
    }

    prep_kernel<<<148, 256>>>(W1, W2, W3, utab, mtab, wideW);
    wd_mma<<<GRID, THREADS, SMEM_BYTES>>>(uids, mids, gender, age, occ, genres,
                                          wideW, wideB, b1, b2, b3, W4, b4, out);
}

// round 13
// speedup vs baseline: 1.2543x; 1.0733x over previous
#include <cuda_runtime.h>
#include <cuda_bf16.h>
#include <stdint.h>

#define NU 6041
#define NM 3953
#define B_TOTAL 1048576
#define NTILES 8192          // 128 rows per CTA-tile
#define GRID 592
#define THREADS 128          // 4 warps, 32 rows/warp
#define AW 28                // u32 words per A row (24 data + 4 pad; 28r mod 32 conflict-free)

typedef unsigned long long u64;
typedef unsigned int u32;
typedef unsigned short u16;

// ---- dynamic smem offsets (bytes) ----
#define OFF_A1    0u        // 4*32*28*4 = 14336
#define OFF_B1F   14336u    // 6144  (fp8 frags: 3kt * 4ntp * 32 * uint4)
#define OFF_B2F   20480u    // 4096  (bf16 frags: 4kt * 2ntp * 32 * uint4)
#define OFF_G     24576u    // 9216
#define OFF_IDS   33792u    // 1024
#define OFF_WU    34816u    // 512
#define OFF_WM    35328u    // 512
#define OFF_B1B   35840u    // 256
#define OFF_B2B   36096u    // 128
#define OFF_WR    36224u    // 96
#define OFF_SC    36320u    // 16
#define SMEM_BYTES 36352

__device__ uint4 gB1p[3 * 4 * 32];  // W1 fp8 B-fragments packed [kt][ntp][lane]
__device__ uint4 gB2p[4 * 2 * 32];  // W2 bf16 B-fragments packed [kt][ntp][lane]
__device__ uint2 gB3[2 * 2 * 32];   // W3 bf16 B-fragments [kt][nt][lane]
__device__ u32   gU[NU * 16];       // per-user 64B row: 8 u32 e4m3 emb + wideW + pad
__device__ u32   gM[NM * 16];       // per-movie row, same layout

// ---------------- helpers ----------------
__device__ __forceinline__ u32 pkbf(float lo, float hi) {
    u32 r; asm("cvt.rn.bf16x2.f32 %0,%1,%2;" : "=r"(r) : "f"(hi), "f"(lo)); return r;
}
__device__ __forceinline__ u32 pk8x4(float f0, float f1, float f2, float f3) {
    u16 lo, hi;
    asm("cvt.rn.satfinite.e4m3x2.f32 %0,%1,%2;" : "=h"(lo) : "f"(f1), "f"(f0));
    asm("cvt.rn.satfinite.e4m3x2.f32 %0,%1,%2;" : "=h"(hi) : "f"(f3), "f"(f2));
    return (u32)lo | ((u32)hi << 16);
}
__device__ __forceinline__ u32 smem_u32(const void* p) {
    u32 a; asm("{ .reg .u64 t; cvta.to.shared.u64 t, %1; cvt.u32.u64 %0, t; }" : "=r"(a) : "l"(p));
    return a;
}
__device__ __forceinline__ void mma16816(float* c, const u32* a, u32 b0, u32 b1) {
    asm("mma.sync.aligned.m16n8k16.row.col.f32.bf16.bf16.f32 "
        "{%0,%1,%2,%3},{%4,%5,%6,%7},{%8,%9},{%0,%1,%2,%3};"
        : "+f"(c[0]), "+f"(c[1]), "+f"(c[2]), "+f"(c[3])
        : "r"(a[0]), "r"(a[1]), "r"(a[2]), "r"(a[3]), "r"(b0), "r"(b1));
}
__device__ __forceinline__ void mma16832(float* c, const u32* a, u32 b0, u32 b1) {
    asm("mma.sync.aligned.m16n8k32.row.col.f32.e4m3.e4m3.f32 "
        "{%0,%1,%2,%3},{%4,%5,%6,%7},{%8,%9},{%0,%1,%2,%3};"
        : "+f"(c[0]), "+f"(c[1]), "+f"(c[2]), "+f"(c[3])
        : "r"(a[0]), "r"(a[1]), "r"(a[2]), "r"(a[3]), "r"(b0), "r"(b1));
}
__device__ __forceinline__ void ldmA(u32* a, u32 saddr) {
    asm volatile("ldmatrix.sync.aligned.m8n8.x4.shared.b16 {%0,%1,%2,%3}, [%4];"
                 : "=r"(a[0]), "=r"(a[1]), "=r"(a[2]), "=r"(a[3]) : "r"(saddr));
}
__device__ __forceinline__ float relu(float x) { return fmaxf(x, 0.f); }

// ---------------- prep: weight fragments + fp8 gather tables ----------------
__global__ void prep_kernel(const float* __restrict__ W1, const float* __restrict__ W2,
                            const float* __restrict__ W3,
                            const float* __restrict__ utab, const float* __restrict__ mtab,
                            const float* __restrict__ wideW) {
    int i = blockIdx.x * blockDim.x + threadIdx.x;
    int stride = gridDim.x * blockDim.x;

    // W1 fp8 packed fragments: two n-tiles per uint4 (m16n8k32 B layout)
    for (int idx = i; idx < 3 * 4 * 32; idx += stride) {
        int lane = idx & 31, ntp = (idx >> 5) & 3, kt = idx >> 7;
        int g = lane >> 2, t = lane & 3;
        int n0 = ntp * 16 + g, n1 = n0 + 8;
        int kb = kt * 32 + 4 * t;
        float v[8];
        #pragma unroll
        for (int j = 0; j < 4; j++) {
            int ka = kb + j, kc = kb + 16 + j;
            v[j]     = (ka < 85) ? W1[ka * 64 + n0] : 0.f;
            v[4 + j] = (kc < 85) ? W1[kc * 64 + n0] : 0.f;
        }
        u32 b0n0 = pk8x4(v[0], v[1], v[2], v[3]);
        u32 b1n0 = pk8x4(v[4], v[5], v[6], v[7]);
        #pragma unroll
        for (int j = 0; j < 4; j++) {
            int ka = kb + j, kc = kb + 16 + j;
            v[j]     = (ka < 85) ? W1[ka * 64 + n1] : 0.f;
            v[4 + j] = (kc < 85) ? W1[kc * 64 + n1] : 0.f;
        }
        u32 b0n1 = pk8x4(v[0], v[1], v[2], v[3]);
        u32 b1n1 = pk8x4(v[4], v[5], v[6], v[7]);
        gB1p[idx] = make_uint4(b0n0, b1n0, b0n1, b1n1);
    }
    // W2 bf16 packed fragments
    for (int idx = i; idx < 4 * 2 * 32; idx += stride) {
        int lane = idx & 31, ntp = (idx >> 5) & 1, kt = idx >> 6;
        int g = lane >> 2, t = lane & 3;
        int n0 = ntp * 16 + g, n1 = n0 + 8;
        int k0 = kt * 16 + t * 2;
        gB2p[idx] = make_uint4(
            pkbf(W2[k0 * 32 + n0],       W2[(k0 + 1) * 32 + n0]),
            pkbf(W2[(k0 + 8) * 32 + n0], W2[(k0 + 9) * 32 + n0]),
            pkbf(W2[k0 * 32 + n1],       W2[(k0 + 1) * 32 + n1]),
            pkbf(W2[(k0 + 8) * 32 + n1], W2[(k0 + 9) * 32 + n1]));
    }
    // W3 bf16 fragments
    for (int idx = i; idx < 2 * 2 * 32; idx += stride) {
        int lane = idx & 31, nt = (idx >> 5) & 1, kt = idx >> 6;
        int g = lane >> 2, t = lane & 3;
        int n = nt * 8 + g;
        int k0 = kt * 16 + t * 2;
        gB3[idx] = make_uint2(pkbf(W3[k0 * 16 + n],       W3[(k0 + 1) * 16 + n]),
                              pkbf(W3[(k0 + 8) * 16 + n], W3[(k0 + 9) * 16 + n]));
    }
    // fp8 gather tables: 2 uint4 emb chunks per id + wide scalar
    for (int idx = i; idx < NU * 2; idx += stride) {
        int id = idx >> 1, j = idx & 1;
        const float* e = utab + id * 32 + j * 16;
        ((uint4*)(gU + id * 16))[j] = make_uint4(
            pk8x4(e[0], e[1], e[2], e[3]),   pk8x4(e[4], e[5], e[6], e[7]),
            pk8x4(e[8], e[9], e[10], e[11]), pk8x4(e[12], e[13], e[14], e[15]));
    }
    for (int idx = i; idx < NM * 2; idx += stride) {
        int id = idx >> 1, j = idx & 1;
        const float* e = mtab + id * 32 + j * 16;
        ((uint4*)(gM + id * 16))[j] = make_uint4(
            pk8x4(e[0], e[1], e[2], e[3]),   pk8x4(e[4], e[5], e[6], e[7]),
            pk8x4(e[8], e[9], e[10], e[11]), pk8x4(e[12], e[13], e[14], e[15]));
    }
    for (int id = i; id < NU; id += stride) gU[id * 16 + 8] = __float_as_uint(wideW[id]);
    for (int id = i; id < NM; id += stride) gM[id * 16 + 8] = __float_as_uint(wideW[NU + id]);
}

// ---------------- main kernel ----------------
__global__ void __launch_bounds__(THREADS, 4)
wd_mma(const int* __restrict__ uids, const int* __restrict__ mids,
       const float* __restrict__ gender, const float* __restrict__ age,
       const float* __restrict__ occ, const float* __restrict__ genres,
       const float* __restrict__ wideW, const float* __restrict__ wideB,
       const float* __restrict__ b1, const float* __restrict__ b2,
       const float* __restrict__ b3, const float* __restrict__ W4,
       const float* __restrict__ b4, float* __restrict__ out)
{
    extern __shared__ __align__(16) char smem[];
    u32*   sA1w  = (u32*)(smem + OFF_A1);
    uint4* sB1p  = (uint4*)(smem + OFF_B1F);
    uint4* sB2p  = (uint4*)(smem + OFF_B2F);
    float* sG    = (float*)(smem + OFF_G);
    int*   sIds  = (int*)(smem + OFF_IDS);
    float* sWU   = (float*)(smem + OFF_WU);
    float* sWM   = (float*)(smem + OFF_WM);
    float* sB1b  = (float*)(smem + OFF_B1B);
    float* sB2b  = (float*)(smem + OFF_B2B);
    float* sWr   = (float*)(smem + OFF_WR);
    float* sSc   = (float*)(smem + OFF_SC);

    const int tid  = threadIdx.x;
    const int wid  = tid >> 5;
    const int lane = tid & 31;
    const int g    = lane >> 2;
    const int t4   = lane & 3;

    // ---- one-time staging ----
    for (int i = tid; i < 3 * 4 * 32; i += THREADS) sB1p[i] = gB1p[i];
    for (int i = tid; i < 4 * 2 * 32; i += THREADS) sB2p[i] = gB2p[i];
    if (tid < 64) sB1b[tid] = b1[tid];
    if (tid < 32) sB2b[tid] = b2[tid];
    if (tid < 21) sWr[tid]  = wideW[NU + NM + tid];
    if (tid == 0) { sSc[0] = b4[0]; sSc[1] = wideB[0]; }

    uint2 rB3[2][2];
    #pragma unroll
    for (int kt = 0; kt < 2; kt++)
        #pragma unroll
        for (int nt = 0; nt < 2; nt++)
            rB3[kt][nt] = gB3[(kt * 2 + nt) * 32 + lane];
    const int c0 = 2 * t4;
    const float b3c0 = b3[c0], b3c1 = b3[c0 + 1], b3c2 = b3[8 + c0], b3c3 = b3[9 + c0];
    const float w4c0 = W4[c0], w4c1 = W4[c0 + 1], w4c2 = W4[8 + c0], w4c3 = W4[9 + c0];
    __syncthreads();

    u32*   myA   = sA1w + wid * (32 * AW);
    float* myG   = sG + wid * 576;
    int*   myIds = sIds + wid * 64;
    float* myWU  = sWU + wid * 32;
    float* myWM  = sWM + wid * 32;

    const u32 aBase = smem_u32(myA);
    const u32 aAddr = aBase + (u32)(((lane & 15) * AW + (lane >> 4) * 4) * 4);

    // ---- prefetch first tile's ids ----
    int pu = 0, pm = 0;
    if (blockIdx.x < NTILES) {
        pu = uids[blockIdx.x * 128 + wid * 32 + lane];
        pm = mids[blockIdx.x * 128 + wid * 32 + lane];
    }

    for (int tile = blockIdx.x; tile < NTILES; tile += gridDim.x) {
        const int R = tile * 128 + wid * 32;
        __syncwarp();

        // ---- genres (coalesced stream) + prefetched ids -> smem ----
        {
            const float2* gb = (const float2*)(genres + (size_t)R * 18);
            float2* mg = (float2*)myG;
            #pragma unroll
            for (int j = 0; j < 9; j++) mg[lane + 32 * j] = gb[lane + 32 * j];
            myIds[lane]      = pu;
            myIds[32 + lane] = pm;
        }
        __syncwarp();

        // ---- fp8 gather: 2 lanes per 32B emb row + wide scalar ----
        {
            const int ch = lane & 1;
            const int r16 = lane >> 1;
            #pragma unroll
            for (int p = 0; p < 2; p++) {
                const int row = r16 + 16 * p;
                const u32* ub = gU + (u32)myIds[row] * 16;
                const u32* mb = gM + (u32)myIds[32 + row] * 16;
                uint4 vu = ((const uint4*)ub)[ch];
                uint4 vm = ((const uint4*)mb)[ch];
                u32* rb = myA + row * AW;
                *(uint4*)(rb + 4 * ch)     = vu;   // words 0..7 : user emb (bytes 0..31)
                *(uint4*)(rb + 8 + 4 * ch) = vm;   // words 8..15: movie emb (bytes 32..63)
                if (ch == 0) {
                    myWU[row] = __uint_as_float(ub[8]);
                    myWM[row] = __uint_as_float(mb[8]);
                }
            }
        }
        __syncwarp();

        // ---- rest features (fp8) + wide path (one row per lane) ----
        float wide;
        {
            const int r = R + lane;
            float fv[21];
            fv[0] = gender[r]; fv[1] = age[r]; fv[2] = occ[r];
            #pragma unroll
            for (int q = 0; q < 9; q++) {
                float2 p = *(const float2*)(myG + lane * 18 + 2 * q);
                fv[3 + 2 * q] = p.x; fv[4 + 2 * q] = p.y;
            }
            wide = sSc[1] + myWU[lane] + myWM[lane];
            #pragma unroll
            for (int i = 0; i < 21; i++) wide = fmaf(fv[i], sWr[i], wide);

            u32 w[8];
            w[0] = pk8x4(fv[0],  fv[1],  fv[2],  fv[3]);
            w[1] = pk8x4(fv[4],  fv[5],  fv[6],  fv[7]);
            w[2] = pk8x4(fv[8],  fv[9],  fv[10], fv[11]);
            w[3] = pk8x4(fv[12], fv[13], fv[14], fv[15]);
            w[4] = pk8x4(fv[16], fv[17], fv[18], fv[19]);
            w[5] = pk8x4(fv[20], 0.f, 0.f, 0.f);
            w[6] = 0u; w[7] = 0u;
            u32* rb = myA + lane * AW + 16;          // bytes 64..95
            *(uint4*)(rb)     = make_uint4(w[0], w[1], w[2], w[3]);
            *(uint4*)(rb + 4) = make_uint4(w[4], w[5], w[6], w[7]);
        }
        __syncwarp();

        // ---- prefetch NEXT tile's ids (hidden under MMA section) ----
        {
            int nt2 = tile + gridDim.x;
            if (nt2 < NTILES) {
                pu = uids[nt2 * 128 + wid * 32 + lane];
                pm = mids[nt2 * 128 + wid * 32 + lane];
            }
        }

        // ---- layer 1 (fp8, k=96 in 3 steps): two m-tiles share each B frag ----
        float acc[2][8][4];
        #pragma unroll
        for (int m = 0; m < 2; m++)
            #pragma unroll
            for (int nt = 0; nt < 8; nt++)
                acc[m][nt][0] = acc[m][nt][1] = acc[m][nt][2] = acc[m][nt][3] = 0.f;
        #pragma unroll
        for (int kt = 0; kt < 3; kt++) {
            u32 a0[4], a1[4];
            ldmA(a0, aAddr + kt * 32u);
            ldmA(a1, aAddr + 16u * AW * 4u + kt * 32u);
            #pragma unroll
            for (int ntp = 0; ntp < 4; ntp++) {
                uint4 q = sB1p[(kt * 4 + ntp) * 32 + lane];
                mma16832(acc[0][2*ntp],     a0, q.x, q.y);
                mma16832(acc[0][2*ntp + 1], a0, q.z, q.w);
                mma16832(acc[1][2*ntp],     a1, q.x, q.y);
                mma16832(acc[1][2*ntp + 1], a1, q.z, q.w);
            }
        }

        // ---- epilogue 1: bias+relu -> bf16 layer-2 A-frags ----
        u32 a2f[2][4][4];
        #pragma unroll
        for (int m = 0; m < 2; m++)
            #pragma unroll
            for (int kt = 0; kt < 4; kt++) {
                int j0 = 2 * kt, j1 = j0 + 1;
                float2 bb0 = *(const float2*)(sB1b + j0 * 8 + t4 * 2);
                float2 bb1 = *(const float2*)(sB1b + j1 * 8 + t4 * 2);
                a2f[m][kt][0] = pkbf(relu(acc[m][j0][0] + bb0.x), relu(acc[m][j0][1] + bb0.y));
                a2f[m][kt][1] = pkbf(relu(acc[m][j0][2] + bb0.x), relu(acc[m][j0][3] + bb0.y));
                a2f[m][kt][2] = pkbf(relu(acc[m][j1][0] + bb1.x), relu(acc[m][j1][1] + bb1.y));
                a2f[m][kt][3] = pkbf(relu(acc[m][j1][2] + bb1.x), relu(acc[m][j1][3] + bb1.y));
            }

        // ---- layer 2 (bf16) ----
        float acc2[2][4][4];
        #pragma unroll
        for (int m = 0; m < 2; m++)
            #pragma unroll
            for (int nt = 0; nt < 4; nt++)
                acc2[m][nt][0] = acc2[m][nt][1] = acc2[m][nt][2] = acc2[m][nt][3] = 0.f;
        #pragma unroll
        for (int kt = 0; kt < 4; kt++)
            #pragma unroll
            for (int ntp = 0; ntp < 2; ntp++) {
                uint4 q = sB2p[(kt * 2 + ntp) * 32 + lane];
                mma16816(acc2[0][2*ntp],     a2f[0][kt], q.x, q.y);
                mma16816(acc2[0][2*ntp + 1], a2f[0][kt], q.z, q.w);
                mma16816(acc2[1][2*ntp],     a2f[1][kt], q.x, q.y);
                mma16816(acc2[1][2*ntp + 1], a2f[1][kt], q.z, q.w);
            }

        // ---- epilogue 2 + layer 3 (bf16, register B) + tail, per m-tile ----
        #pragma unroll
        for (int m = 0; m < 2; m++) {
            u32 a3f[2][4];
            #pragma unroll
            for (int kt = 0; kt < 2; kt++) {
                int j0 = 2 * kt, j1 = j0 + 1;
                float2 bb0 = *(const float2*)(sB2b + j0 * 8 + t4 * 2);
                float2 bb1 = *(const float2*)(sB2b + j1 * 8 + t4 * 2);
                a3f[kt][0] = pkbf(relu(acc2[m][j0][0] + bb0.x), relu(acc2[m][j0][1] + bb0.y));
                a3f[kt][1] = pkbf(relu(acc2[m][j0][2] + bb0.x), relu(acc2[m][j0][3] + bb0.y));
                a3f[kt][2] = pkbf(relu(acc2[m][j1][0] + bb1.x), relu(acc2[m][j1][1] + bb1.y));
                a3f[kt][3] = pkbf(relu(acc2[m][j1][2] + bb1.x), relu(acc2[m][j1][3] + bb1.y));
            }
            float acc3[2][4];
            #pragma unroll
            for (int nt = 0; nt < 2; nt++)
                acc3[nt][0] = acc3[nt][1] = acc3[nt][2] = acc3[nt][3] = 0.f;
            #pragma unroll
            for (int kt = 0; kt < 2; kt++)
                #pragma unroll
                for (int nt = 0; nt < 2; nt++)
                    mma16816(acc3[nt], a3f[kt], rB3[kt][nt].x, rB3[kt][nt].y);

            float dpg, dph;
            dpg  = relu(acc3[0][0] + b3c0) * w4c0;
            dpg  = fmaf(relu(acc3[0][1] + b3c1), w4c1, dpg);
            dpg  = fmaf(relu(acc3[1][0] + b3c2), w4c2, dpg);
            dpg  = fmaf(relu(acc3[1][1] + b3c3), w4c3, dpg);
            dph  = relu(acc3[0][2] + b3c0) * w4c0;
            dph  = fmaf(relu(acc3[0][3] + b3c1), w4c1, dph);
            dph  = fmaf(relu(acc3[1][2] + b3c2), w4c2, dph);
            dph  = fmaf(relu(acc3[1][3] + b3c3), w4c3, dph);
            dpg += __shfl_xor_sync(0xffffffffu, dpg, 1);
            dpg += __shfl_xor_sync(0xffffffffu, dpg, 2);
            dph += __shfl_xor_sync(0xffffffffu, dph, 1);
            dph += __shfl_xor_sync(0xffffffffu, dph, 2);

            float wg = __shfl_sync(0xffffffffu, wide, m * 16 + g);
            float wh = __shfl_sync(0xffffffffu, wide, m * 16 + 8 + g);
            if (t4 == 0) {
                float zg = wg + dpg + sSc[0];
                float zh = wh + dph + sSc[0];
                out[R + m * 16 + g]     = 1.f / (1.f + expf(-zg));
                out[R + m * 16 + 8 + g] = 1.f / (1.f + expf(-zh));
            }
        }
    }
}

extern "C" void kernel_launch(void* const* d_in, const int* in_sizes, int n_in,
                              void* d_out, int out_size) {
    const int*   uids   = (const int*)  d_in[0];
    const int*   mids   = (const int*)  d_in[1];
    const float* gender = (const float*)d_in[2];
    const float* age    = (const float*)d_in[3];
    const float* occ    = (const float*)d_in[4];
    const float* genres = (const float*)d_in[5];
    const float* wideW  = (const float*)d_in[6];
    const float* wideB  = (const float*)d_in[7];
    const float* utab   = (const float*)d_in[8];
    const float* mtab   = (const float*)d_in[9];
    const float* W1     = (const float*)d_in[10];
    const float* b1     = (const float*)d_in[11];
    const float* W2     = (const float*)d_in[12];
    const float* b2     = (const float*)d_in[13];
    const float* W3     = (const float*)d_in[14];
    const float* b3     = (const float*)d_in[15];
    const float* W4     = (const float*)d_in[16];
    const float* b4     = (const float*)d_in[17];
    float* out = (float*)d_out;

    static int inited = 0;
    if (!inited) {
        cudaFuncSetAttribute(wd_mma, cudaFuncAttributeMaxDynamicSharedMemorySize, SMEM_BYTES);
        inited = 1;
    }

    prep_kernel<<<148, 256>>>(W1, W2, W3, utab, mtab, wideW);
    wd_mma<<<GRID, THREADS, SMEM_BYTES>>>(uids, mids, gender, age, occ, genres,
                                          wideW, wideB, b1, b2, b3, W4, b4, out);
}

// round 14
// speedup vs baseline: 1.3064x; 1.0416x over previous
#include <cuda_runtime.h>
#include <cuda_bf16.h>
#include <stdint.h>

#define NU 6041
#define NM 3953
#define B_TOTAL 1048576
#define NTILES 8192          // 128 rows per CTA-tile
#define GRID 592
#define THREADS 128          // 4 warps, 32 rows/warp
#define AW 28                // u32 words per A row (24 data + 4 pad)

typedef unsigned long long u64;
typedef unsigned int u32;
typedef unsigned short u16;

// ---- dynamic smem offsets (bytes) ----
#define OFF_A1    0u        // 4*32*28*4 = 14336
#define OFF_B1F   14336u    // 6144  (fp8 frags: 3kt * 4ntp * 32 * uint4)
#define OFF_B2F   20480u    // 5120  (bf16 frags: 5kt * 2ntp * 32 * uint4)
#define OFF_G     25600u    // 9216
#define OFF_IDS   34816u    // 1024
#define OFF_WU    35840u    // 512
#define OFF_WM    36352u    // 512
#define OFF_WR    36864u    // 96
#define OFF_SC    36960u    // 16
#define SMEM_BYTES 36992

__device__ uint4 gB1p[3 * 4 * 32];  // W1 fp8 B-fragments (row k=85 carries b1)
__device__ uint4 gB2p[5 * 2 * 32];  // W2 bf16 B-fragments (kt=4 row k=64 carries b2)
__device__ uint2 gB3[3 * 2 * 32];   // W3 bf16 B-fragments (kt=2 row k=32 carries b3)
__device__ u32   gU[NU * 16];       // per-user 64B row: 8 u32 e4m3 emb + wideW
__device__ u32   gM[NM * 16];       // per-movie row, same layout

// ---------------- helpers ----------------
__device__ __forceinline__ u32 pkbf(float lo, float hi) {
    u32 r; asm("cvt.rn.bf16x2.f32 %0,%1,%2;" : "=r"(r) : "f"(hi), "f"(lo)); return r;
}
__device__ __forceinline__ u32 pk8x4(float f0, float f1, float f2, float f3) {
    u16 lo, hi;
    asm("cvt.rn.satfinite.e4m3x2.f32 %0,%1,%2;" : "=h"(lo) : "f"(f1), "f"(f0));
    asm("cvt.rn.satfinite.e4m3x2.f32 %0,%1,%2;" : "=h"(hi) : "f"(f3), "f"(f2));
    return (u32)lo | ((u32)hi << 16);
}
__device__ __forceinline__ u32 smem_u32(const void* p) {
    u32 a; asm("{ .reg .u64 t; cvta.to.shared.u64 t, %1; cvt.u32.u64 %0, t; }" : "=r"(a) : "l"(p));
    return a;
}
__device__ __forceinline__ void mma16816(float* c, const u32* a, u32 b0, u32 b1) {
    asm("mma.sync.aligned.m16n8k16.row.col.f32.bf16.bf16.f32 "
        "{%0,%1,%2,%3},{%4,%5,%6,%7},{%8,%9},{%0,%1,%2,%3};"
        : "+f"(c[0]), "+f"(c[1]), "+f"(c[2]), "+f"(c[3])
        : "r"(a[0]), "r"(a[1]), "r"(a[2]), "r"(a[3]), "r"(b0), "r"(b1));
}
__device__ __forceinline__ void mma16832(float* c, const u32* a, u32 b0, u32 b1) {
    asm("mma.sync.aligned.m16n8k32.row.col.f32.e4m3.e4m3.f32 "
        "{%0,%1,%2,%3},{%4,%5,%6,%7},{%8,%9},{%0,%1,%2,%3};"
        : "+f"(c[0]), "+f"(c[1]), "+f"(c[2]), "+f"(c[3])
        : "r"(a[0]), "r"(a[1]), "r"(a[2]), "r"(a[3]), "r"(b0), "r"(b1));
}
__device__ __forceinline__ void ldmA(u32* a, u32 saddr) {
    asm volatile("ldmatrix.sync.aligned.m8n8.x4.shared.b16 {%0,%1,%2,%3}, [%4];"
                 : "=r"(a[0]), "=r"(a[1]), "=r"(a[2]), "=r"(a[3]) : "r"(saddr));
}
__device__ __forceinline__ float relu(float x) { return fmaxf(x, 0.f); }

// ---------------- prep ----------------
__global__ void prep_kernel(const float* __restrict__ W1, const float* __restrict__ W2,
                            const float* __restrict__ W3,
                            const float* __restrict__ b1, const float* __restrict__ b2,
                            const float* __restrict__ b3,
                            const float* __restrict__ utab, const float* __restrict__ mtab,
                            const float* __restrict__ wideW) {
    int i = blockIdx.x * blockDim.x + threadIdx.x;
    int stride = gridDim.x * blockDim.x;

    // W1 fp8 packed fragments; row k=85 carries b1 (A provides const 1.0 there)
    for (int idx = i; idx < 3 * 4 * 32; idx += stride) {
        int lane = idx & 31, ntp = (idx >> 5) & 3, kt = idx >> 7;
        int g = lane >> 2, t = lane & 3;
        int n0 = ntp * 16 + g, n1 = n0 + 8;
        int kb = kt * 32 + 4 * t;
        float v[8];
        #pragma unroll
        for (int j = 0; j < 4; j++) {
            int ka = kb + j, kc = kb + 16 + j;
            v[j]     = (ka < 85) ? W1[ka * 64 + n0] : ((ka == 85) ? b1[n0] : 0.f);
            v[4 + j] = (kc < 85) ? W1[kc * 64 + n0] : ((kc == 85) ? b1[n0] : 0.f);
        }
        u32 b0n0 = pk8x4(v[0], v[1], v[2], v[3]);
        u32 b1n0 = pk8x4(v[4], v[5], v[6], v[7]);
        #pragma unroll
        for (int j = 0; j < 4; j++) {
            int ka = kb + j, kc = kb + 16 + j;
            v[j]     = (ka < 85) ? W1[ka * 64 + n1] : ((ka == 85) ? b1[n1] : 0.f);
            v[4 + j] = (kc < 85) ? W1[kc * 64 + n1] : ((kc == 85) ? b1[n1] : 0.f);
        }
        gB1p[idx] = make_uint4(b0n0, b1n0, pk8x4(v[0], v[1], v[2], v[3]),
                               pk8x4(v[4], v[5], v[6], v[7]));
    }
    // W2 bf16 packed fragments, kt=4 carries b2 at k=64
    for (int idx = i; idx < 5 * 2 * 32; idx += stride) {
        int lane = idx & 31, ntp = (idx >> 5) & 1, kt = idx >> 6;
        int g = lane >> 2, t = lane & 3;
        int n0 = ntp * 16 + g, n1 = n0 + 8;
        int k0 = kt * 16 + t * 2;
        auto w2v = [&](int k, int n) -> float {
            return (k < 64) ? W2[k * 32 + n] : ((k == 64) ? b2[n] : 0.f);
        };
        gB2p[idx] = make_uint4(
            pkbf(w2v(k0, n0),     w2v(k0 + 1, n0)),
            pkbf(w2v(k0 + 8, n0), w2v(k0 + 9, n0)),
            pkbf(w2v(k0, n1),     w2v(k0 + 1, n1)),
            pkbf(w2v(k0 + 8, n1), w2v(k0 + 9, n1)));
    }
    // W3 bf16 fragments, kt=2 carries b3 at k=32
    for (int idx = i; idx < 3 * 2 * 32; idx += stride) {
        int lane = idx & 31, nt = (idx >> 5) & 1, kt = idx >> 6;
        int g = lane >> 2, t = lane & 3;
        int n = nt * 8 + g;
        int k0 = kt * 16 + t * 2;
        auto w3v = [&](int k, int nn) -> float {
            return (k < 32) ? W3[k * 16 + nn] : ((k == 32) ? b3[nn] : 0.f);
        };
        gB3[idx] = make_uint2(pkbf(w3v(k0, n),     w3v(k0 + 1, n)),
                              pkbf(w3v(k0 + 8, n), w3v(k0 + 9, n)));
    }
    // fp8 gather tables
    for (int idx = i; idx < NU * 2; idx += stride) {
        int id = idx >> 1, j = idx & 1;
        const float* e = utab + id * 32 + j * 16;
        ((uint4*)(gU + id * 16))[j] = make_uint4(
            pk8x4(e[0], e[1], e[2], e[3]),   pk8x4(e[4], e[5], e[6], e[7]),
            pk8x4(e[8], e[9], e[10], e[11]), pk8x4(e[12], e[13], e[14], e[15]));
    }
    for (int idx = i; idx < NM * 2; idx += stride) {
        int id = idx >> 1, j = idx & 1;
        const float* e = mtab + id * 32 + j * 16;
        ((uint4*)(gM + id * 16))[j] = make_uint4(
            pk8x4(e[0], e[1], e[2], e[3]),   pk8x4(e[4], e[5], e[6], e[7]),
            pk8x4(e[8], e[9], e[10], e[11]), pk8x4(e[12], e[13], e[14], e[15]));
    }
    for (int id = i; id < NU; id += stride) gU[id * 16 + 8] = __float_as_uint(wideW[id]);
    for (int id = i; id < NM; id += stride) gM[id * 16 + 8] = __float_as_uint(wideW[NU + id]);
}

// ---------------- main kernel ----------------
__global__ void __launch_bounds__(THREADS, 4)
wd_mma(const int* __restrict__ uids, const int* __restrict__ mids,
       const float* __restrict__ gender, const float* __restrict__ age,
       const float* __restrict__ occ, const float* __restrict__ genres,
       const float* __restrict__ wideW, const float* __restrict__ wideB,
       const float* __restrict__ W4, const float* __restrict__ b4,
       float* __restrict__ out)
{
    extern __shared__ __align__(16) char smem[];
    u32*   sA1w  = (u32*)(smem + OFF_A1);
    uint4* sB1p  = (uint4*)(smem + OFF_B1F);
    uint4* sB2p  = (uint4*)(smem + OFF_B2F);
    float* sG    = (float*)(smem + OFF_G);
    int*   sIds  = (int*)(smem + OFF_IDS);
    float* sWU   = (float*)(smem + OFF_WU);
    float* sWM   = (float*)(smem + OFF_WM);
    float* sWr   = (float*)(smem + OFF_WR);
    float* sSc   = (float*)(smem + OFF_SC);

    const int tid  = threadIdx.x;
    const int wid  = tid >> 5;
    const int lane = tid & 31;
    const int g    = lane >> 2;
    const int t4   = lane & 3;

    // ---- one-time staging ----
    for (int i = tid; i < 3 * 4 * 32; i += THREADS) sB1p[i] = gB1p[i];
    for (int i = tid; i < 5 * 2 * 32; i += THREADS) sB2p[i] = gB2p[i];
    if (tid < 21) sWr[tid]  = wideW[NU + NM + tid];
    if (tid == 0) { sSc[0] = b4[0]; sSc[1] = wideB[0]; }

    uint2 rB3[3][2];
    #pragma unroll
    for (int kt = 0; kt < 3; kt++)
        #pragma unroll
        for (int nt = 0; nt < 2; nt++)
            rB3[kt][nt] = gB3[(kt * 2 + nt) * 32 + lane];
    const int c0 = 2 * t4;
    const float w4c0 = W4[c0], w4c1 = W4[c0 + 1], w4c2 = W4[8 + c0], w4c3 = W4[9 + c0];

    // constant A-fragment for the bias k-tiles: local col 0 = 1.0 (bf16), rest 0
    const u32 aConst = (t4 == 0) ? 0x00003F80u : 0u;
    u32 acf[4]; acf[0] = aConst; acf[1] = aConst; acf[2] = 0u; acf[3] = 0u;
    __syncthreads();

    u32*   myA   = sA1w + wid * (32 * AW);
    float* myG   = sG + wid * 576;
    int*   myIds = sIds + wid * 64;
    float* myWU  = sWU + wid * 32;
    float* myWM  = sWM + wid * 32;

    const u32 aBase = smem_u32(myA);
    const u32 aAddr = aBase + (u32)(((lane & 15) * AW + (lane >> 4) * 4) * 4);

    // ---- prefetch first tile's ids ----
    int pu = 0, pm = 0;
    if (blockIdx.x < NTILES) {
        pu = uids[blockIdx.x * 128 + wid * 32 + lane];
        pm = mids[blockIdx.x * 128 + wid * 32 + lane];
    }

    for (int tile = blockIdx.x; tile < NTILES; tile += gridDim.x) {
        const int R = tile * 128 + wid * 32;
        __syncwarp();

        // ---- genres (coalesced) + prefetched ids -> smem ----
        {
            const float2* gb = (const float2*)(genres + (size_t)R * 18);
            float2* mg = (float2*)myG;
            #pragma unroll
            for (int j = 0; j < 9; j++) mg[lane + 32 * j] = gb[lane + 32 * j];
            myIds[lane]      = pu;
            myIds[32 + lane] = pm;
        }
        __syncwarp();

        // ---- fp8 gather: 2 lanes per 32B emb row + wide scalar ----
        {
            const int ch = lane & 1;
            const int r16 = lane >> 1;
            #pragma unroll
            for (int p = 0; p < 2; p++) {
                const int row = r16 + 16 * p;
                const u32* ub = gU + (u32)myIds[row] * 16;
                const u32* mb = gM + (u32)myIds[32 + row] * 16;
                uint4 vu = ((const uint4*)ub)[ch];
                uint4 vm = ((const uint4*)mb)[ch];
                u32* rb = myA + row * AW;
                *(uint4*)(rb + 4 * ch)     = vu;
                *(uint4*)(rb + 8 + 4 * ch) = vm;
                if (ch == 0) {
                    myWU[row] = __uint_as_float(ub[8]);
                    myWM[row] = __uint_as_float(mb[8]);
                }
            }
        }
        __syncwarp();

        // ---- rest features (fp8, const-1 at k=85) + wide path ----
        float wide;
        {
            const int r = R + lane;
            float fv[21];
            fv[0] = gender[r]; fv[1] = age[r]; fv[2] = occ[r];
            #pragma unroll
            for (int q = 0; q < 9; q++) {
                float2 p = *(const float2*)(myG + lane * 18 + 2 * q);
                fv[3 + 2 * q] = p.x; fv[4 + 2 * q] = p.y;
            }
            wide = sSc[1] + myWU[lane] + myWM[lane];
            #pragma unroll
            for (int i = 0; i < 21; i++) wide = fmaf(fv[i], sWr[i], wide);

            u32 w[8];
            w[0] = pk8x4(fv[0],  fv[1],  fv[2],  fv[3]);
            w[1] = pk8x4(fv[4],  fv[5],  fv[6],  fv[7]);
            w[2] = pk8x4(fv[8],  fv[9],  fv[10], fv[11]);
            w[3] = pk8x4(fv[12], fv[13], fv[14], fv[15]);
            w[4] = pk8x4(fv[16], fv[17], fv[18], fv[19]);
            w[5] = pk8x4(fv[20], 1.0f, 0.f, 0.f);   // k=85 const 1.0 -> b1 row
            w[6] = 0u; w[7] = 0u;
            u32* rb = myA + lane * AW + 16;
            *(uint4*)(rb)     = make_uint4(w[0], w[1], w[2], w[3]);
            *(uint4*)(rb + 4) = make_uint4(w[4], w[5], w[6], w[7]);
        }
        __syncwarp();

        // ---- prefetch NEXT tile's ids ----
        {
            int nt2 = tile + gridDim.x;
            if (nt2 < NTILES) {
                pu = uids[nt2 * 128 + wid * 32 + lane];
                pm = mids[nt2 * 128 + wid * 32 + lane];
            }
        }

        // ---- layer 1 (fp8, k=96, bias folded) ----
        float acc[2][8][4];
        #pragma unroll
        for (int m = 0; m < 2; m++)
            #pragma unroll
            for (int nt = 0; nt < 8; nt++)
                acc[m][nt][0] = acc[m][nt][1] = acc[m][nt][2] = acc[m][nt][3] = 0.f;
        #pragma unroll
        for (int kt = 0; kt < 3; kt++) {
            u32 a0[4], a1[4];
            ldmA(a0, aAddr + kt * 32u);
            ldmA(a1, aAddr + 16u * AW * 4u + kt * 32u);
            #pragma unroll
            for (int ntp = 0; ntp < 4; ntp++) {
                uint4 q = sB1p[(kt * 4 + ntp) * 32 + lane];
                mma16832(acc[0][2*ntp],     a0, q.x, q.y);
                mma16832(acc[0][2*ntp + 1], a0, q.z, q.w);
                mma16832(acc[1][2*ntp],     a1, q.x, q.y);
                mma16832(acc[1][2*ntp + 1], a1, q.z, q.w);
            }
        }

        // ---- epilogue 1: relu -> bf16 A-frags (no bias add) ----
        u32 a2f[2][4][4];
        #pragma unroll
        for (int m = 0; m < 2; m++)
            #pragma unroll
            for (int kt = 0; kt < 4; kt++) {
                int j0 = 2 * kt, j1 = j0 + 1;
                a2f[m][kt][0] = pkbf(relu(acc[m][j0][0]), relu(acc[m][j0][1]));
                a2f[m][kt][1] = pkbf(relu(acc[m][j0][2]), relu(acc[m][j0][3]));
                a2f[m][kt][2] = pkbf(relu(acc[m][j1][0]), relu(acc[m][j1][1]));
                a2f[m][kt][3] = pkbf(relu(acc[m][j1][2]), relu(acc[m][j1][3]));
            }

        // ---- layer 2 (bf16, k=80: kt=4 is the bias tile with const A) ----
        float acc2[2][4][4];
        #pragma unroll
        for (int m = 0; m < 2; m++)
            #pragma unroll
            for (int nt = 0; nt < 4; nt++)
                acc2[m][nt][0] = acc2[m][nt][1] = acc2[m][nt][2] = acc2[m][nt][3] = 0.f;
        #pragma unroll
        for (int kt = 0; kt < 4; kt++)
            #pragma unroll
            for (int ntp = 0; ntp < 2; ntp++) {
                uint4 q = sB2p[(kt * 2 + ntp) * 32 + lane];
                mma16816(acc2[0][2*ntp],     a2f[0][kt], q.x, q.y);
                mma16816(acc2[0][2*ntp + 1], a2f[0][kt], q.z, q.w);
                mma16816(acc2[1][2*ntp],     a2f[1][kt], q.x, q.y);
                mma16816(acc2[1][2*ntp + 1], a2f[1][kt], q.z, q.w);
            }
        #pragma unroll
        for (int ntp = 0; ntp < 2; ntp++) {
            uint4 q = sB2p[(4 * 2 + ntp) * 32 + lane];
            mma16816(acc2[0][2*ntp],     acf, q.x, q.y);
            mma16816(acc2[0][2*ntp + 1], acf, q.z, q.w);
            mma16816(acc2[1][2*ntp],     acf, q.x, q.y);
            mma16816(acc2[1][2*ntp + 1], acf, q.z, q.w);
        }

        // ---- epilogue 2 + layer 3 (k=48 incl. bias tile) + tail ----
        #pragma unroll
        for (int m = 0; m < 2; m++) {
            u32 a3f[2][4];
            #pragma unroll
            for (int kt = 0; kt < 2; kt++) {
                int j0 = 2 * kt, j1 = j0 + 1;
                a3f[kt][0] = pkbf(relu(acc2[m][j0][0]), relu(acc2[m][j0][1]));
                a3f[kt][1] = pkbf(relu(acc2[m][j0][2]), relu(acc2[m][j0][3]));
                a3f[kt][2] = pkbf(relu(acc2[m][j1][0]), relu(acc2[m][j1][1]));
                a3f[kt][3] = pkbf(relu(acc2[m][j1][2]), relu(acc2[m][j1][3]));
            }
            float acc3[2][4];
            #pragma unroll
            for (int nt = 0; nt < 2; nt++)
                acc3[nt][0] = acc3[nt][1] = acc3[nt][2] = acc3[nt][3] = 0.f;
            #pragma unroll
            for (int kt = 0; kt < 2; kt++)
                #pragma unroll
                for (int nt = 0; nt < 2; nt++)
                    mma16816(acc3[nt], a3f[kt], rB3[kt][nt].x, rB3[kt][nt].y);
            #pragma unroll
            for (int nt = 0; nt < 2; nt++)
                mma16816(acc3[nt], acf, rB3[2][nt].x, rB3[2][nt].y);

            float dpg, dph;
            dpg  = relu(acc3[0][0]) * w4c0;
            dpg  = fmaf(relu(acc3[0][1]), w4c1, dpg);
            dpg  = fmaf(relu(acc3[1][0]), w4c2, dpg);
            dpg  = fmaf(relu(acc3[1][1]), w4c3, dpg);
            dph  = relu(acc3[0][2]) * w4c0;
            dph  = fmaf(relu(acc3[0][3]), w4c1, dph);
            dph  = fmaf(relu(acc3[1][2]), w4c2, dph);
            dph  = fmaf(relu(acc3[1][3]), w4c3, dph);
            dpg += __shfl_xor_sync(0xffffffffu, dpg, 1);
            dpg += __shfl_xor_sync(0xffffffffu, dpg, 2);
            dph += __shfl_xor_sync(0xffffffffu, dph, 1);
            dph += __shfl_xor_sync(0xffffffffu, dph, 2);

            float wg = __shfl_sync(0xffffffffu, wide, m * 16 + g);
            float wh = __shfl_sync(0xffffffffu, wide, m * 16 + 8 + g);
            if (t4 == 0) {
                float zg = wg + dpg + sSc[0];
                float zh = wh + dph + sSc[0];
                out[R + m * 16 + g]     = __fdividef(1.f, 1.f + __expf(-zg));
                out[R + m * 16 + 8 + g] = __fdividef(1.f, 1.f + __expf(-zh));
            }
        }
    }
}

extern "C" void kernel_launch(void* const* d_in, const int* in_sizes, int n_in,
                              void* d_out, int out_size) {
    const int*   uids   = (const int*)  d_in[0];
    const int*   mids   = (const int*)  d_in[1];
    const float* gender = (const float*)d_in[2];
    const float* age    = (const float*)d_in[3];
    const float* occ    = (const float*)d_in[4];
    const float* genres = (const float*)d_in[5];
    const float* wideW  = (const float*)d_in[6];
    const float* wideB  = (const float*)d_in[7];
    const float* utab   = (const float*)d_in[8];
    const float* mtab   = (const float*)d_in[9];
    const float* W1     = (const float*)d_in[10];
    const float* b1     = (const float*)d_in[11];
    const float* W2     = (const float*)d_in[12];
    const float* b2     = (const float*)d_in[13];
    const float* W3     = (const float*)d_in[14];
    const float* b3     = (const float*)d_in[15];
    const float* W4     = (const float*)d_in[16];
    const float* b4     = (const float*)d_in[17];
    float* out = (float*)d_out;

    static int inited = 0;
    if (!inited) {
        cudaFuncSetAttribute(wd_mma, cudaFuncAttributeMaxDynamicSharedMemorySize, SMEM_BYTES);
        inited = 1;
    }

    prep_kernel<<<148, 256>>>(W1, W2, W3, b1, b2, b3, utab, mtab, wideW);
    wd_mma<<<GRID, THREADS, SMEM_BYTES>>>(uids, mids, gender, age, occ, genres,
                                          wideW, wideB, W4, b4, out);
}

// round 15
// speedup vs baseline: 1.3209x; 1.0111x over previous
#include <cuda_runtime.h>
#include <cuda_bf16.h>
#include <stdint.h>

#define NU 6041
#define NM 3953
#define B_TOTAL 1048576
#define NTILES 8192          // 128 rows per CTA-tile
#define GRID 592
#define THREADS 128          // 4 warps, 32 rows/warp
#define AW 28                // u32 words per A row (24 data + 4 pad)

typedef unsigned long long u64;
typedef unsigned int u32;
typedef unsigned short u16;

// ---- dynamic smem offsets (bytes) ----
#define OFF_A1    0u        // 4*32*28*4 = 14336
#define OFF_B1F   14336u    // 6144  (fp8 frags: 3kt * 4ntp * 32 * uint4)
#define OFF_B2F   20480u    // 5120  (bf16 frags: 5kt * 2ntp * 32 * uint4)
#define OFF_G     25600u    // 9216
#define OFF_WU    34816u    // 512
#define OFF_WM    35328u    // 512
#define OFF_WR    35840u    // 96
#define OFF_SC    35936u    // 16
#define SMEM_BYTES 35968

__device__ uint4 gB1p[3 * 4 * 32];  // W1 fp8 B-fragments (row k=85 carries b1)
__device__ uint4 gB2p[5 * 2 * 32];  // W2 bf16 B-fragments (kt=4 row k=64 carries b2)
__device__ uint2 gB3[3 * 2 * 32];   // W3 bf16 B-fragments (kt=2 row k=32 carries b3)
__device__ u32   gU[NU * 16];       // per-user 64B row: 8 u32 e4m3 emb + wideW
__device__ u32   gM[NM * 16];       // per-movie row, same layout

// ---------------- helpers ----------------
__device__ __forceinline__ u32 pkbf(float lo, float hi) {
    u32 r; asm("cvt.rn.bf16x2.f32 %0,%1,%2;" : "=r"(r) : "f"(hi), "f"(lo)); return r;
}
__device__ __forceinline__ u32 maxbf2(u32 v) {
    u32 r; asm("max.bf16x2 %0,%1,%2;" : "=r"(r) : "r"(v), "r"(0u)); return r;
}
__device__ __forceinline__ u32 pk8x4(float f0, float f1, float f2, float f3) {
    u16 lo, hi;
    asm("cvt.rn.satfinite.e4m3x2.f32 %0,%1,%2;" : "=h"(lo) : "f"(f1), "f"(f0));
    asm("cvt.rn.satfinite.e4m3x2.f32 %0,%1,%2;" : "=h"(hi) : "f"(f3), "f"(f2));
    return (u32)lo | ((u32)hi << 16);
}
__device__ __forceinline__ u32 smem_u32(const void* p) {
    u32 a; asm("{ .reg .u64 t; cvta.to.shared.u64 t, %1; cvt.u32.u64 %0, t; }" : "=r"(a) : "l"(p));
    return a;
}
__device__ __forceinline__ void mma16816(float* c, const u32* a, u32 b0, u32 b1) {
    asm("mma.sync.aligned.m16n8k16.row.col.f32.bf16.bf16.f32 "
        "{%0,%1,%2,%3},{%4,%5,%6,%7},{%8,%9},{%0,%1,%2,%3};"
        : "+f"(c[0]), "+f"(c[1]), "+f"(c[2]), "+f"(c[3])
        : "r"(a[0]), "r"(a[1]), "r"(a[2]), "r"(a[3]), "r"(b0), "r"(b1));
}
__device__ __forceinline__ void mma16832(float* c, const u32* a, u32 b0, u32 b1) {
    asm("mma.sync.aligned.m16n8k32.row.col.f32.e4m3.e4m3.f32 "
        "{%0,%1,%2,%3},{%4,%5,%6,%7},{%8,%9},{%0,%1,%2,%3};"
        : "+f"(c[0]), "+f"(c[1]), "+f"(c[2]), "+f"(c[3])
        : "r"(a[0]), "r"(a[1]), "r"(a[2]), "r"(a[3]), "r"(b0), "r"(b1));
}
__device__ __forceinline__ void ldmA(u32* a, u32 saddr) {
    asm volatile("ldmatrix.sync.aligned.m8n8.x4.shared.b16 {%0,%1,%2,%3}, [%4];"
                 : "=r"(a[0]), "=r"(a[1]), "=r"(a[2]), "=r"(a[3]) : "r"(saddr));
}
__device__ __forceinline__ float relu(float x) { return fmaxf(x, 0.f); }

// ---------------- prep ----------------
__global__ void prep_kernel(const float* __restrict__ W1, const float* __restrict__ W2,
                            const float* __restrict__ W3,
                            const float* __restrict__ b1, const float* __restrict__ b2,
                            const float* __restrict__ b3,
                            const float* __restrict__ utab, const float* __restrict__ mtab,
                            const float* __restrict__ wideW) {
    int i = blockIdx.x * blockDim.x + threadIdx.x;
    int stride = gridDim.x * blockDim.x;

    // W1 fp8 packed fragments; row k=85 carries b1 (A provides const 1.0 there)
    for (int idx = i; idx < 3 * 4 * 32; idx += stride) {
        int lane = idx & 31, ntp = (idx >> 5) & 3, kt = idx >> 7;
        int g = lane >> 2, t = lane & 3;
        int n0 = ntp * 16 + g, n1 = n0 + 8;
        int kb = kt * 32 + 4 * t;
        float v[8];
        #pragma unroll
        for (int j = 0; j < 4; j++) {
            int ka = kb + j, kc = kb + 16 + j;
            v[j]     = (ka < 85) ? W1[ka * 64 + n0] : ((ka == 85) ? b1[n0] : 0.f);
            v[4 + j] = (kc < 85) ? W1[kc * 64 + n0] : ((kc == 85) ? b1[n0] : 0.f);
        }
        u32 b0n0 = pk8x4(v[0], v[1], v[2], v[3]);
        u32 b1n0 = pk8x4(v[4], v[5], v[6], v[7]);
        #pragma unroll
        for (int j = 0; j < 4; j++) {
            int ka = kb + j, kc = kb + 16 + j;
            v[j]     = (ka < 85) ? W1[ka * 64 + n1] : ((ka == 85) ? b1[n1] : 0.f);
            v[4 + j] = (kc < 85) ? W1[kc * 64 + n1] : ((kc == 85) ? b1[n1] : 0.f);
        }
        gB1p[idx] = make_uint4(b0n0, b1n0, pk8x4(v[0], v[1], v[2], v[3]),
                               pk8x4(v[4], v[5], v[6], v[7]));
    }
    // W2 bf16 packed fragments, kt=4 carries b2 at k=64
    for (int idx = i; idx < 5 * 2 * 32; idx += stride) {
        int lane = idx & 31, ntp = (idx >> 5) & 1, kt = idx >> 6;
        int g = lane >> 2, t = lane & 3;
        int n0 = ntp * 16 + g, n1 = n0 + 8;
        int k0 = kt * 16 + t * 2;
        auto w2v = [&](int k, int n) -> float {
            return (k < 64) ? W2[k * 32 + n] : ((k == 64) ? b2[n] : 0.f);
        };
        gB2p[idx] = make_uint4(
            pkbf(w2v(k0, n0),     w2v(k0 + 1, n0)),
            pkbf(w2v(k0 + 8, n0), w2v(k0 + 9, n0)),
            pkbf(w2v(k0, n1),     w2v(k0 + 1, n1)),
            pkbf(w2v(k0 + 8, n1), w2v(k0 + 9, n1)));
    }
    // W3 bf16 fragments, kt=2 carries b3 at k=32
    for (int idx = i; idx < 3 * 2 * 32; idx += stride) {
        int lane = idx & 31, nt = (idx >> 5) & 1, kt = idx >> 6;
        int g = lane >> 2, t = lane & 3;
        int n = nt * 8 + g;
        int k0 = kt * 16 + t * 2;
        auto w3v = [&](int k, int nn) -> float {
            return (k < 32) ? W3[k * 16 + nn] : ((k == 32) ? b3[nn] : 0.f);
        };
        gB3[idx] = make_uint2(pkbf(w3v(k0, n),     w3v(k0 + 1, n)),
                              pkbf(w3v(k0 + 8, n), w3v(k0 + 9, n)));
    }
    // fp8 gather tables
    for (int idx = i; idx < NU * 2; idx += stride) {
        int id = idx >> 1, j = idx & 1;
        const float* e = utab + id * 32 + j * 16;
        ((uint4*)(gU + id * 16))[j] = make_uint4(
            pk8x4(e[0], e[1], e[2], e[3]),   pk8x4(e[4], e[5], e[6], e[7]),
            pk8x4(e[8], e[9], e[10], e[11]), pk8x4(e[12], e[13], e[14], e[15]));
    }
    for (int idx = i; idx < NM * 2; idx += stride) {
        int id = idx >> 1, j = idx & 1;
        const float* e = mtab + id * 32 + j * 16;
        ((uint4*)(gM + id * 16))[j] = make_uint4(
            pk8x4(e[0], e[1], e[2], e[3]),   pk8x4(e[4], e[5], e[6], e[7]),
            pk8x4(e[8], e[9], e[10], e[11]), pk8x4(e[12], e[13], e[14], e[15]));
    }
    for (int id = i; id < NU; id += stride) gU[id * 16 + 8] = __float_as_uint(wideW[id]);
    for (int id = i; id < NM; id += stride) gM[id * 16 + 8] = __float_as_uint(wideW[NU + id]);
}

// ---------------- main kernel ----------------
__global__ void __launch_bounds__(THREADS, 4)
wd_mma(const int* __restrict__ uids, const int* __restrict__ mids,
       const float* __restrict__ gender, const float* __restrict__ age,
       const float* __restrict__ occ, const float* __restrict__ genres,
       const float* __restrict__ wideW, const float* __restrict__ wideB,
       const float* __restrict__ W4, const float* __restrict__ b4,
       float* __restrict__ out)
{
    extern __shared__ __align__(16) char smem[];
    u32*   sA1w  = (u32*)(smem + OFF_A1);
    uint4* sB1p  = (uint4*)(smem + OFF_B1F);
    uint4* sB2p  = (uint4*)(smem + OFF_B2F);
    float* sG    = (float*)(smem + OFF_G);
    float* sWU   = (float*)(smem + OFF_WU);
    float* sWM   = (float*)(smem + OFF_WM);
    float* sWr   = (float*)(smem + OFF_WR);
    float* sSc   = (float*)(smem + OFF_SC);

    const int tid  = threadIdx.x;
    const int wid  = tid >> 5;
    const int lane = tid & 31;
    const int g    = lane >> 2;
    const int t4   = lane & 3;

    // ---- one-time staging ----
    for (int i = tid; i < 3 * 4 * 32; i += THREADS) sB1p[i] = gB1p[i];
    for (int i = tid; i < 5 * 2 * 32; i += THREADS) sB2p[i] = gB2p[i];
    if (tid < 21) sWr[tid]  = wideW[NU + NM + tid];
    if (tid == 0) { sSc[0] = b4[0]; sSc[1] = wideB[0]; }

    uint2 rB3[3][2];
    #pragma unroll
    for (int kt = 0; kt < 3; kt++)
        #pragma unroll
        for (int nt = 0; nt < 2; nt++)
            rB3[kt][nt] = gB3[(kt * 2 + nt) * 32 + lane];
    const int c0 = 2 * t4;
    const float w4c0 = W4[c0], w4c1 = W4[c0 + 1], w4c2 = W4[8 + c0], w4c3 = W4[9 + c0];

    // constant A-fragment for the bias k-tiles: local col 0 = 1.0 (bf16), rest 0
    const u32 aConst = (t4 == 0) ? 0x00003F80u : 0u;
    u32 acf[4]; acf[0] = aConst; acf[1] = aConst; acf[2] = 0u; acf[3] = 0u;
    __syncthreads();

    u32*   myA   = sA1w + wid * (32 * AW);
    float* myG   = sG + wid * 576;
    float* myWU  = sWU + wid * 32;
    float* myWM  = sWM + wid * 32;

    const u32 aBase = smem_u32(myA);
    const u32 aAddr = aBase + (u32)(((lane & 15) * AW + (lane >> 4) * 4) * 4);

    // ---- prefetch first tile's ids ----
    int pu = 0, pm = 0;
    if (blockIdx.x < NTILES) {
        pu = uids[blockIdx.x * 128 + wid * 32 + lane];
        pm = mids[blockIdx.x * 128 + wid * 32 + lane];
    }

    const int ch  = lane & 1;     // 16B chunk within 32B emb row
    const int r16 = lane >> 1;    // row index 0..15

    for (int tile = blockIdx.x; tile < NTILES; tile += gridDim.x) {
        const int R = tile * 128 + wid * 32;
        __syncwarp();   // prior iteration's ldmA reads done before new stores

        // ---- gather ids via shfl (no smem round-trip), issue big LDGs FIRST ----
        const int u0 = __shfl_sync(0xffffffffu, pu, r16);
        const int m0 = __shfl_sync(0xffffffffu, pm, r16);
        const int u1 = __shfl_sync(0xffffffffu, pu, r16 + 16);
        const int m1 = __shfl_sync(0xffffffffu, pm, r16 + 16);
        const u32* ub0 = gU + (u32)u0 * 16;
        const u32* mb0 = gM + (u32)m0 * 16;
        const u32* ub1 = gU + (u32)u1 * 16;
        const u32* mb1 = gM + (u32)m1 * 16;
        uint4 vu0 = ((const uint4*)ub0)[ch];
        uint4 vm0 = ((const uint4*)mb0)[ch];
        uint4 vu1 = ((const uint4*)ub1)[ch];
        uint4 vm1 = ((const uint4*)mb1)[ch];
        float wu0 = 0.f, wm0 = 0.f, wu1 = 0.f, wm1 = 0.f;
        if (ch == 0) {
            wu0 = __uint_as_float(ub0[8]); wm0 = __uint_as_float(mb0[8]);
            wu1 = __uint_as_float(ub1[8]); wm1 = __uint_as_float(mb1[8]);
        }

        // ---- genres (coalesced stream) ----
        float2 gg[9];
        {
            const float2* gb = (const float2*)(genres + (size_t)R * 18);
            #pragma unroll
            for (int j = 0; j < 9; j++) gg[j] = gb[lane + 32 * j];
        }

        // ---- stores: gather rows + wide scalars + genres ----
        {
            u32* rb0 = myA + r16 * AW;
            u32* rb1 = myA + (r16 + 16) * AW;
            *(uint4*)(rb0 + 4 * ch)     = vu0;
            *(uint4*)(rb0 + 8 + 4 * ch) = vm0;
            *(uint4*)(rb1 + 4 * ch)     = vu1;
            *(uint4*)(rb1 + 8 + 4 * ch) = vm1;
            if (ch == 0) {
                myWU[r16] = wu0;      myWM[r16] = wm0;
                myWU[r16 + 16] = wu1; myWM[r16 + 16] = wm1;
            }
            float2* mg = (float2*)myG;
            #pragma unroll
            for (int j = 0; j < 9; j++) mg[lane + 32 * j] = gg[j];
        }
        __syncwarp();

        // ---- rest features (fp8, const-1 at k=85) + wide path ----
        float wide;
        {
            float fv[21];
            fv[0] = gender[R + lane]; fv[1] = age[R + lane]; fv[2] = occ[R + lane];
            #pragma unroll
            for (int q = 0; q < 9; q++) {
                float2 p = *(const float2*)(myG + lane * 18 + 2 * q);
                fv[3 + 2 * q] = p.x; fv[4 + 2 * q] = p.y;
            }
            float wa = sSc[1] + myWU[lane] + myWM[lane];
            float wb = 0.f, wc = 0.f;
            #pragma unroll
            for (int i = 0; i < 7; i++) {
                wa = fmaf(fv[3 * i],     sWr[3 * i],     wa);
                wb = fmaf(fv[3 * i + 1], sWr[3 * i + 1], wb);
                wc = fmaf(fv[3 * i + 2], sWr[3 * i + 2], wc);
            }
            wide = wa + wb + wc;

            u32 w[8];
            w[0] = pk8x4(fv[0],  fv[1],  fv[2],  fv[3]);
            w[1] = pk8x4(fv[4],  fv[5],  fv[6],  fv[7]);
            w[2] = pk8x4(fv[8],  fv[9],  fv[10], fv[11]);
            w[3] = pk8x4(fv[12], fv[13], fv[14], fv[15]);
            w[4] = pk8x4(fv[16], fv[17], fv[18], fv[19]);
            w[5] = pk8x4(fv[20], 1.0f, 0.f, 0.f);   // k=85 const 1.0 -> b1 row
            w[6] = 0u; w[7] = 0u;
            u32* rb = myA + lane * AW + 16;
            *(uint4*)(rb)     = make_uint4(w[0], w[1], w[2], w[3]);
            *(uint4*)(rb + 4) = make_uint4(w[4], w[5], w[6], w[7]);
        }
        __syncwarp();

        // ---- prefetch NEXT tile's ids (hidden under MMA section) ----
        {
            int nt2 = tile + gridDim.x;
            if (nt2 < NTILES) {
                pu = uids[nt2 * 128 + wid * 32 + lane];
                pm = mids[nt2 * 128 + wid * 32 + lane];
            }
        }

        // ---- layer 1 (fp8, k=96, bias folded) ----
        float acc[2][8][4];
        #pragma unroll
        for (int m = 0; m < 2; m++)
            #pragma unroll
            for (int nt = 0; nt < 8; nt++)
                acc[m][nt][0] = acc[m][nt][1] = acc[m][nt][2] = acc[m][nt][3] = 0.f;
        #pragma unroll
        for (int kt = 0; kt < 3; kt++) {
            u32 a0[4], a1[4];
            ldmA(a0, aAddr + kt * 32u);
            ldmA(a1, aAddr + 16u * AW * 4u + kt * 32u);
            #pragma unroll
            for (int ntp = 0; ntp < 4; ntp++) {
                uint4 q = sB1p[(kt * 4 + ntp) * 32 + lane];
                mma16832(acc[0][2*ntp],     a0, q.x, q.y);
                mma16832(acc[0][2*ntp + 1], a0, q.z, q.w);
                mma16832(acc[1][2*ntp],     a1, q.x, q.y);
                mma16832(acc[1][2*ntp + 1], a1, q.z, q.w);
            }
        }

        // ---- epilogue 1: pack then packed-relu -> bf16 A-frags ----
        u32 a2f[2][4][4];
        #pragma unroll
        for (int m = 0; m < 2; m++)
            #pragma unroll
            for (int kt = 0; kt < 4; kt++) {
                int j0 = 2 * kt, j1 = j0 + 1;
                a2f[m][kt][0] = maxbf2(pkbf(acc[m][j0][0], acc[m][j0][1]));
                a2f[m][kt][1] = maxbf2(pkbf(acc[m][j0][2], acc[m][j0][3]));
                a2f[m][kt][2] = maxbf2(pkbf(acc[m][j1][0], acc[m][j1][1]));
                a2f[m][kt][3] = maxbf2(pkbf(acc[m][j1][2], acc[m][j1][3]));
            }

        // ---- layer 2 (bf16, k=80: kt=4 is the bias tile with const A) ----
        float acc2[2][4][4];
        #pragma unroll
        for (int m = 0; m < 2; m++)
            #pragma unroll
            for (int nt = 0; nt < 4; nt++)
                acc2[m][nt][0] = acc2[m][nt][1] = acc2[m][nt][2] = acc2[m][nt][3] = 0.f;
        #pragma unroll
        for (int kt = 0; kt < 4; kt++)
            #pragma unroll
            for (int ntp = 0; ntp < 2; ntp++) {
                uint4 q = sB2p[(kt * 2 + ntp) * 32 + lane];
                mma16816(acc2[0][2*ntp],     a2f[0][kt], q.x, q.y);
                mma16816(acc2[0][2*ntp + 1], a2f[0][kt], q.z, q.w);
                mma16816(acc2[1][2*ntp],     a2f[1][kt], q.x, q.y);
                mma16816(acc2[1][2*ntp + 1], a2f[1][kt], q.z, q.w);
            }
        #pragma unroll
        for (int ntp = 0; ntp < 2; ntp++) {
            uint4 q = sB2p[(4 * 2 + ntp) * 32 + lane];
            mma16816(acc2[0][2*ntp],     acf, q.x, q.y);
            mma16816(acc2[0][2*ntp + 1], acf, q.z, q.w);
            mma16816(acc2[1][2*ntp],     acf, q.x, q.y);
            mma16816(acc2[1][2*ntp + 1], acf, q.z, q.w);
        }

        // ---- epilogue 2 + layer 3 (k=48 incl. bias tile) + tail ----
        #pragma unroll
        for (int m = 0; m < 2; m++) {
            u32 a3f[2][4];
            #pragma unroll
            for (int kt = 0; kt < 2; kt++) {
                int j0 = 2 * kt, j1 = j0 + 1;
                a3f[kt][0] = maxbf2(pkbf(acc2[m][j0][0], acc2[m][j0][1]));
                a3f[kt][1] = maxbf2(pkbf(acc2[m][j0][2], acc2[m][j0][3]));
                a3f[kt][2] = maxbf2(pkbf(acc2[m][j1][0], acc2[m][j1][1]));
                a3f[kt][3] = maxbf2(pkbf(acc2[m][j1][2], acc2[m][j1][3]));
            }
            float acc3[2][4];
            #pragma unroll
            for (int nt = 0; nt < 2; nt++)
                acc3[nt][0] = acc3[nt][1] = acc3[nt][2] = acc3[nt][3] = 0.f;
            #pragma unroll
            for (int kt = 0; kt < 2; kt++)
                #pragma unroll
                for (int nt = 0; nt < 2; nt++)
                    mma16816(acc3[nt], a3f[kt], rB3[kt][nt].x, rB3[kt][nt].y);
            #pragma unroll
            for (int nt = 0; nt < 2; nt++)
                mma16816(acc3[nt], acf, rB3[2][nt].x, rB3[2][nt].y);

            float dpg, dph;
            dpg  = relu(acc3[0][0]) * w4c0;
            dpg  = fmaf(relu(acc3[0][1]), w4c1, dpg);
            dpg  = fmaf(relu(acc3[1][0]), w4c2, dpg);
            dpg  = fmaf(relu(acc3[1][1]), w4c3, dpg);
            dph  = relu(acc3[0][2]) * w4c0;
            dph  = fmaf(relu(acc3[0][3]), w4c1, dph);
            dph  = fmaf(relu(acc3[1][2]), w4c2, dph);
            dph  = fmaf(relu(acc3[1][3]), w4c3, dph);
            dpg += __shfl_xor_sync(0xffffffffu, dpg, 1);
            dpg += __shfl_xor_sync(0xffffffffu, dpg, 2);
            dph += __shfl_xor_sync(0xffffffffu, dph, 1);
            dph += __shfl_xor_sync(0xffffffffu, dph, 2);

            float wg = __shfl_sync(0xffffffffu, wide, m * 16 + g);
            float wh = __shfl_sync(0xffffffffu, wide, m * 16 + 8 + g);
            if (t4 == 0) {
                float zg = wg + dpg + sSc[0];
                float zh = wh + dph + sSc[0];
                out[R + m * 16 + g]     = __fdividef(1.f, 1.f + __expf(-zg));
                out[R + m * 16 + 8 + g] = __fdividef(1.f, 1.f + __expf(-zh));
            }
        }
    }
}

extern "C" void kernel_launch(void* const* d_in, const int* in_sizes, int n_in,
                              void* d_out, int out_size) {
    const int*   uids   = (const int*)  d_in[0];
    const int*   mids   = (const int*)  d_in[1];
    const float* gender = (const float*)d_in[2];
    const float* age    = (const float*)d_in[3];
    const float* occ    = (const float*)d_in[4];
    const float* genres = (const float*)d_in[5];
    const float* wideW  = (const float*)d_in[6];
    const float* wideB  = (const float*)d_in[7];
    const float* utab   = (const float*)d_in[8];
    const float* mtab   = (const float*)d_in[9];
    const float* W1     = (const float*)d_in[10];
    const float* b1     = (const float*)d_in[11];
    const float* W2     = (const float*)d_in[12];
    const float* b2     = (const float*)d_in[13];
    const float* W3     = (const float*)d_in[14];
    const float* b3     = (const float*)d_in[15];
    const float* W4     = (const float*)d_in[16];
    const float* b4     = (const float*)d_in[17];
    float* out = (float*)d_out;

    static int inited = 0;
    if (!inited) {
        cudaFuncSetAttribute(wd_mma, cudaFuncAttributeMaxDynamicSharedMemorySize, SMEM_BYTES);
        inited = 1;
    }

    prep_kernel<<<148, 256>>>(W1, W2, W3, b1, b2, b3, utab, mtab, wideW);
    wd_mma<<<GRID, THREADS, SMEM_BYTES>>>(uids, mids, gender, age, occ, genres,
                                          wideW, wideB, W4, b4, out);
}

// round 16
// speedup vs baseline: 1.3766x; 1.0422x over previous
#include <cuda_runtime.h>
#include <cuda_bf16.h>
#include <stdint.h>

#define NU 6041
#define NM 3953
#define B_TOTAL 1048576
#define NTILES 8192          // 128 rows per CTA-tile
#define GRID 592
#define THREADS 128          // 4 warps, 32 rows/warp
#define AW 28                // u32 words per A row (24 data + 4 pad)

typedef unsigned long long u64;
typedef unsigned int u32;
typedef unsigned short u16;

// ---- dynamic smem offsets (bytes) ----
#define OFF_A1    0u        // 4*32*28*4 = 14336
#define OFF_B1F   14336u    // 6144  (fp8 frags: 3kt * 4ntp * 32 * uint4)
#define OFF_B2F   20480u    // 4096  (bf16 frags: 4kt * 2ntp * 32 * uint4)
#define OFF_G     24576u    // 9216
#define OFF_WU    33792u    // 512
#define OFF_WM    34304u    // 512
#define OFF_WR    34816u    // 96
#define OFF_SC    34912u    // 16
#define SMEM_BYTES 34944

__device__ uint4 gB1p[3 * 4 * 32];  // W1 fp8 B-fragments (row k=85 carries b1)
__device__ uint4 gB2p[4 * 2 * 32];  // W2 bf16 B-fragments
__device__ uint2 gB3[2 * 2 * 32];   // W3 bf16 B-fragments
__device__ u32   gU[NU * 16];       // per-user 64B row: 8 u32 e4m3 emb + wideW
__device__ u32   gM[NM * 16];       // per-movie row, same layout

// ---------------- helpers ----------------
__device__ __forceinline__ u32 pkbf(float lo, float hi) {
    u32 r; asm("cvt.rn.bf16x2.f32 %0,%1,%2;" : "=r"(r) : "f"(hi), "f"(lo)); return r;
}
__device__ __forceinline__ u32 maxbf2(u32 v) {
    u32 r; asm("max.bf16x2 %0,%1,%2;" : "=r"(r) : "r"(v), "r"(0u)); return r;
}
__device__ __forceinline__ u32 pk8x4(float f0, float f1, float f2, float f3) {
    u16 lo, hi;
    asm("cvt.rn.satfinite.e4m3x2.f32 %0,%1,%2;" : "=h"(lo) : "f"(f1), "f"(f0));
    asm("cvt.rn.satfinite.e4m3x2.f32 %0,%1,%2;" : "=h"(hi) : "f"(f3), "f"(f2));
    return (u32)lo | ((u32)hi << 16);
}
__device__ __forceinline__ u32 smem_u32(const void* p) {
    u32 a; asm("{ .reg .u64 t; cvta.to.shared.u64 t, %1; cvt.u32.u64 %0, t; }" : "=r"(a) : "l"(p));
    return a;
}
__device__ __forceinline__ void mma16816(float* c, const u32* a, u32 b0, u32 b1) {
    asm("mma.sync.aligned.m16n8k16.row.col.f32.bf16.bf16.f32 "
        "{%0,%1,%2,%3},{%4,%5,%6,%7},{%8,%9},{%0,%1,%2,%3};"
        : "+f"(c[0]), "+f"(c[1]), "+f"(c[2]), "+f"(c[3])
        : "r"(a[0]), "r"(a[1]), "r"(a[2]), "r"(a[3]), "r"(b0), "r"(b1));
}
__device__ __forceinline__ void mma16832(float* c, const u32* a, u32 b0, u32 b1) {
    asm("mma.sync.aligned.m16n8k32.row.col.f32.e4m3.e4m3.f32 "
        "{%0,%1,%2,%3},{%4,%5,%6,%7},{%8,%9},{%0,%1,%2,%3};"
        : "+f"(c[0]), "+f"(c[1]), "+f"(c[2]), "+f"(c[3])
        : "r"(a[0]), "r"(a[1]), "r"(a[2]), "r"(a[3]), "r"(b0), "r"(b1));
}
__device__ __forceinline__ void ldmA(u32* a, u32 saddr) {
    asm volatile("ldmatrix.sync.aligned.m8n8.x4.shared.b16 {%0,%1,%2,%3}, [%4];"
                 : "=r"(a[0]), "=r"(a[1]), "=r"(a[2]), "=r"(a[3]) : "r"(saddr));
}
__device__ __forceinline__ float relu(float x) { return fmaxf(x, 0.f); }

// ---------------- prep ----------------
__global__ void prep_kernel(const float* __restrict__ W1, const float* __restrict__ W2,
                            const float* __restrict__ W3,
                            const float* __restrict__ b1,
                            const float* __restrict__ utab, const float* __restrict__ mtab,
                            const float* __restrict__ wideW) {
    int i = blockIdx.x * blockDim.x + threadIdx.x;
    int stride = gridDim.x * blockDim.x;

    // W1 fp8 packed fragments; row k=85 carries b1 (A provides const 1.0 there)
    for (int idx = i; idx < 3 * 4 * 32; idx += stride) {
        int lane = idx & 31, ntp = (idx >> 5) & 3, kt = idx >> 7;
        int g = lane >> 2, t = lane & 3;
        int n0 = ntp * 16 + g, n1 = n0 + 8;
        int kb = kt * 32 + 4 * t;
        float v[8];
        #pragma unroll
        for (int j = 0; j < 4; j++) {
            int ka = kb + j, kc = kb + 16 + j;
            v[j]     = (ka < 85) ? W1[ka * 64 + n0] : ((ka == 85) ? b1[n0] : 0.f);
            v[4 + j] = (kc < 85) ? W1[kc * 64 + n0] : ((kc == 85) ? b1[n0] : 0.f);
        }
        u32 b0n0 = pk8x4(v[0], v[1], v[2], v[3]);
        u32 b1n0 = pk8x4(v[4], v[5], v[6], v[7]);
        #pragma unroll
        for (int j = 0; j < 4; j++) {
            int ka = kb + j, kc = kb + 16 + j;
            v[j]     = (ka < 85) ? W1[ka * 64 + n1] : ((ka == 85) ? b1[n1] : 0.f);
            v[4 + j] = (kc < 85) ? W1[kc * 64 + n1] : ((kc == 85) ? b1[n1] : 0.f);
        }
        gB1p[idx] = make_uint4(b0n0, b1n0, pk8x4(v[0], v[1], v[2], v[3]),
                               pk8x4(v[4], v[5], v[6], v[7]));
    }
    // W2 bf16 packed fragments (no bias tile)
    for (int idx = i; idx < 4 * 2 * 32; idx += stride) {
        int lane = idx & 31, ntp = (idx >> 5) & 1, kt = idx >> 6;
        int g = lane >> 2, t = lane & 3;
        int n0 = ntp * 16 + g, n1 = n0 + 8;
        int k0 = kt * 16 + t * 2;
        gB2p[idx] = make_uint4(
            pkbf(W2[k0 * 32 + n0],       W2[(k0 + 1) * 32 + n0]),
            pkbf(W2[(k0 + 8) * 32 + n0], W2[(k0 + 9) * 32 + n0]),
            pkbf(W2[k0 * 32 + n1],       W2[(k0 + 1) * 32 + n1]),
            pkbf(W2[(k0 + 8) * 32 + n1], W2[(k0 + 9) * 32 + n1]));
    }
    // W3 bf16 fragments (no bias tile)
    for (int idx = i; idx < 2 * 2 * 32; idx += stride) {
        int lane = idx & 31, nt = (idx >> 5) & 1, kt = idx >> 6;
        int g = lane >> 2, t = lane & 3;
        int n = nt * 8 + g;
        int k0 = kt * 16 + t * 2;
        gB3[idx] = make_uint2(pkbf(W3[k0 * 16 + n],       W3[(k0 + 1) * 16 + n]),
                              pkbf(W3[(k0 + 8) * 16 + n], W3[(k0 + 9) * 16 + n]));
    }
    // fp8 gather tables
    for (int idx = i; idx < NU * 2; idx += stride) {
        int id = idx >> 1, j = idx & 1;
        const float* e = utab + id * 32 + j * 16;
        ((uint4*)(gU + id * 16))[j] = make_uint4(
            pk8x4(e[0], e[1], e[2], e[3]),   pk8x4(e[4], e[5], e[6], e[7]),
            pk8x4(e[8], e[9], e[10], e[11]), pk8x4(e[12], e[13], e[14], e[15]));
    }
    for (int idx = i; idx < NM * 2; idx += stride) {
        int id = idx >> 1, j = idx & 1;
        const float* e = mtab + id * 32 + j * 16;
        ((uint4*)(gM + id * 16))[j] = make_uint4(
            pk8x4(e[0], e[1], e[2], e[3]),   pk8x4(e[4], e[5], e[6], e[7]),
            pk8x4(e[8], e[9], e[10], e[11]), pk8x4(e[12], e[13], e[14], e[15]));
    }
    for (int id = i; id < NU; id += stride) gU[id * 16 + 8] = __float_as_uint(wideW[id]);
    for (int id = i; id < NM; id += stride) gM[id * 16 + 8] = __float_as_uint(wideW[NU + id]);
}

// ---------------- main kernel ----------------
__global__ void __launch_bounds__(THREADS, 4)
wd_mma(const int* __restrict__ uids, const int* __restrict__ mids,
       const float* __restrict__ gender, const float* __restrict__ age,
       const float* __restrict__ occ, const float* __restrict__ genres,
       const float* __restrict__ wideW, const float* __restrict__ wideB,
       const float* __restrict__ b2, const float* __restrict__ b3,
       const float* __restrict__ W4, const float* __restrict__ b4,
       float* __restrict__ out)
{
    extern __shared__ __align__(16) char smem[];
    u32*   sA1w  = (u32*)(smem + OFF_A1);
    uint4* sB1p  = (uint4*)(smem + OFF_B1F);
    uint4* sB2p  = (uint4*)(smem + OFF_B2F);
    float* sG    = (float*)(smem + OFF_G);
    float* sWU   = (float*)(smem + OFF_WU);
    float* sWM   = (float*)(smem + OFF_WM);
    float* sWr   = (float*)(smem + OFF_WR);
    float* sSc   = (float*)(smem + OFF_SC);

    const int tid  = threadIdx.x;
    const int wid  = tid >> 5;
    const int lane = tid & 31;
    const int g    = lane >> 2;
    const int t4   = lane & 3;

    // ---- one-time staging ----
    for (int i = tid; i < 3 * 4 * 32; i += THREADS) sB1p[i] = gB1p[i];
    for (int i = tid; i < 4 * 2 * 32; i += THREADS) sB2p[i] = gB2p[i];
    if (tid < 21) sWr[tid]  = wideW[NU + NM + tid];
    if (tid == 0) { sSc[0] = b4[0]; sSc[1] = wideB[0]; }

    uint2 rB3[2][2];
    #pragma unroll
    for (int kt = 0; kt < 2; kt++)
        #pragma unroll
        for (int nt = 0; nt < 2; nt++)
            rB3[kt][nt] = gB3[(kt * 2 + nt) * 32 + lane];
    const int c0 = 2 * t4;
    const float w4c0 = W4[c0], w4c1 = W4[c0 + 1], w4c2 = W4[8 + c0], w4c3 = W4[9 + c0];

    // per-lane bias constants for accumulator init (column-only -> lane-resident)
    float b2v[4][2], b3v[2][2];
    #pragma unroll
    for (int nt = 0; nt < 4; nt++) {
        b2v[nt][0] = b2[nt * 8 + c0];
        b2v[nt][1] = b2[nt * 8 + c0 + 1];
    }
    #pragma unroll
    for (int nt = 0; nt < 2; nt++) {
        b3v[nt][0] = b3[nt * 8 + c0];
        b3v[nt][1] = b3[nt * 8 + c0 + 1];
    }
    __syncthreads();

    u32*   myA   = sA1w + wid * (32 * AW);
    float* myG   = sG + wid * 576;
    float* myWU  = sWU + wid * 32;
    float* myWM  = sWM + wid * 32;

    const u32 aBase = smem_u32(myA);
    const u32 aAddr = aBase + (u32)(((lane & 15) * AW + (lane >> 4) * 4) * 4);

    // ---- prefetch first tile's ids ----
    int pu = 0, pm = 0;
    if (blockIdx.x < NTILES) {
        pu = uids[blockIdx.x * 128 + wid * 32 + lane];
        pm = mids[blockIdx.x * 128 + wid * 32 + lane];
    }

    const int ch  = lane & 1;     // 16B chunk within 32B emb row
    const int r16 = lane >> 1;    // row index 0..15

    for (int tile = blockIdx.x; tile < NTILES; tile += gridDim.x) {
        const int R = tile * 128 + wid * 32;
        __syncwarp();   // prior iteration's ldmA reads done before new stores

        // ---- gather ids via shfl, issue big LDGs FIRST ----
        const int u0 = __shfl_sync(0xffffffffu, pu, r16);
        const int m0 = __shfl_sync(0xffffffffu, pm, r16);
        const int u1 = __shfl_sync(0xffffffffu, pu, r16 + 16);
        const int m1 = __shfl_sync(0xffffffffu, pm, r16 + 16);
        const u32* ub0 = gU + (u32)u0 * 16;
        const u32* mb0 = gM + (u32)m0 * 16;
        const u32* ub1 = gU + (u32)u1 * 16;
        const u32* mb1 = gM + (u32)m1 * 16;
        uint4 vu0 = ((const uint4*)ub0)[ch];
        uint4 vm0 = ((const uint4*)mb0)[ch];
        uint4 vu1 = ((const uint4*)ub1)[ch];
        uint4 vm1 = ((const uint4*)mb1)[ch];
        float wu0 = 0.f, wm0 = 0.f, wu1 = 0.f, wm1 = 0.f;
        if (ch == 0) {
            wu0 = __uint_as_float(ub0[8]); wm0 = __uint_as_float(mb0[8]);
            wu1 = __uint_as_float(ub1[8]); wm1 = __uint_as_float(mb1[8]);
        }

        // ---- genres (coalesced stream) ----
        float2 gg[9];
        {
            const float2* gb = (const float2*)(genres + (size_t)R * 18);
            #pragma unroll
            for (int j = 0; j < 9; j++) gg[j] = gb[lane + 32 * j];
        }

        // ---- stores: gather rows + wide scalars + genres ----
        {
            u32* rb0 = myA + r16 * AW;
            u32* rb1 = myA + (r16 + 16) * AW;
            *(uint4*)(rb0 + 4 * ch)     = vu0;
            *(uint4*)(rb0 + 8 + 4 * ch) = vm0;
            *(uint4*)(rb1 + 4 * ch)     = vu1;
            *(uint4*)(rb1 + 8 + 4 * ch) = vm1;
            if (ch == 0) {
                myWU[r16] = wu0;      myWM[r16] = wm0;
                myWU[r16 + 16] = wu1; myWM[r16 + 16] = wm1;
            }
            float2* mg = (float2*)myG;
            #pragma unroll
            for (int j = 0; j < 9; j++) mg[lane + 32 * j] = gg[j];
        }
        __syncwarp();

        // ---- rest features (fp8, const-1 at k=85) + wide path ----
        float wide;
        {
            float fv[21];
            fv[0] = gender[R + lane]; fv[1] = age[R + lane]; fv[2] = occ[R + lane];
            #pragma unroll
            for (int q = 0; q < 9; q++) {
                float2 p = *(const float2*)(myG + lane * 18 + 2 * q);
                fv[3 + 2 * q] = p.x; fv[4 + 2 * q] = p.y;
            }
            float wa = sSc[1] + myWU[lane] + myWM[lane];
            float wb = 0.f, wc = 0.f;
            #pragma unroll
            for (int i = 0; i < 7; i++) {
                wa = fmaf(fv[3 * i],     sWr[3 * i],     wa);
                wb = fmaf(fv[3 * i + 1], sWr[3 * i + 1], wb);
                wc = fmaf(fv[3 * i + 2], sWr[3 * i + 2], wc);
            }
            wide = wa + wb + wc;

            u32 w[8];
            w[0] = pk8x4(fv[0],  fv[1],  fv[2],  fv[3]);
            w[1] = pk8x4(fv[4],  fv[5],  fv[6],  fv[7]);
            w[2] = pk8x4(fv[8],  fv[9],  fv[10], fv[11]);
            w[3] = pk8x4(fv[12], fv[13], fv[14], fv[15]);
            w[4] = pk8x4(fv[16], fv[17], fv[18], fv[19]);
            w[5] = pk8x4(fv[20], 1.0f, 0.f, 0.f);   // k=85 const 1.0 -> b1 row
            w[6] = 0u; w[7] = 0u;
            u32* rb = myA + lane * AW + 16;
            *(uint4*)(rb)     = make_uint4(w[0], w[1], w[2], w[3]);
            *(uint4*)(rb + 4) = make_uint4(w[4], w[5], w[6], w[7]);
        }
        __syncwarp();

        // ---- prefetch NEXT tile's ids (hidden under MMA section) ----
        {
            int nt2 = tile + gridDim.x;
            if (nt2 < NTILES) {
                pu = uids[nt2 * 128 + wid * 32 + lane];
                pm = mids[nt2 * 128 + wid * 32 + lane];
            }
        }

        // ---- layer 1 (fp8, k=96, bias folded at k=85) ----
        float acc[2][8][4];
        #pragma unroll
        for (int m = 0; m < 2; m++)
            #pragma unroll
            for (int nt = 0; nt < 8; nt++)
                acc[m][nt][0] = acc[m][nt][1] = acc[m][nt][2] = acc[m][nt][3] = 0.f;
        #pragma unroll
        for (int kt = 0; kt < 3; kt++) {
            u32 a0[4], a1[4];
            ldmA(a0, aAddr + kt * 32u);
            ldmA(a1, aAddr + 16u * AW * 4u + kt * 32u);
            #pragma unroll
            for (int ntp = 0; ntp < 4; ntp++) {
                uint4 q = sB1p[(kt * 4 + ntp) * 32 + lane];
                mma16832(acc[0][2*ntp],     a0, q.x, q.y);
                mma16832(acc[0][2*ntp + 1], a0, q.z, q.w);
                mma16832(acc[1][2*ntp],     a1, q.x, q.y);
                mma16832(acc[1][2*ntp + 1], a1, q.z, q.w);
            }
        }

        // ---- epilogue 1: pack then packed-relu -> bf16 A-frags ----
        u32 a2f[2][4][4];
        #pragma unroll
        for (int m = 0; m < 2; m++)
            #pragma unroll
            for (int kt = 0; kt < 4; kt++) {
                int j0 = 2 * kt, j1 = j0 + 1;
                a2f[m][kt][0] = maxbf2(pkbf(acc[m][j0][0], acc[m][j0][1]));
                a2f[m][kt][1] = maxbf2(pkbf(acc[m][j0][2], acc[m][j0][3]));
                a2f[m][kt][2] = maxbf2(pkbf(acc[m][j1][0], acc[m][j1][1]));
                a2f[m][kt][3] = maxbf2(pkbf(acc[m][j1][2], acc[m][j1][3]));
            }

        // ---- layer 2 (bf16, k=64; bias via accumulator init) ----
        float acc2[2][4][4];
        #pragma unroll
        for (int m = 0; m < 2; m++)
            #pragma unroll
            for (int nt = 0; nt < 4; nt++) {
                acc2[m][nt][0] = b2v[nt][0];
                acc2[m][nt][1] = b2v[nt][1];
                acc2[m][nt][2] = b2v[nt][0];
                acc2[m][nt][3] = b2v[nt][1];
            }
        #pragma unroll
        for (int kt = 0; kt < 4; kt++)
            #pragma unroll
            for (int ntp = 0; ntp < 2; ntp++) {
                uint4 q = sB2p[(kt * 2 + ntp) * 32 + lane];
                mma16816(acc2[0][2*ntp],     a2f[0][kt], q.x, q.y);
                mma16816(acc2[0][2*ntp + 1], a2f[0][kt], q.z, q.w);
                mma16816(acc2[1][2*ntp],     a2f[1][kt], q.x, q.y);
                mma16816(acc2[1][2*ntp + 1], a2f[1][kt], q.z, q.w);
            }

        // ---- epilogue 2 + layer 3 (k=32; bias via init) + tail ----
        #pragma unroll
        for (int m = 0; m < 2; m++) {
            u32 a3f[2][4];
            #pragma unroll
            for (int kt = 0; kt < 2; kt++) {
                int j0 = 2 * kt, j1 = j0 + 1;
                a3f[kt][0] = maxbf2(pkbf(acc2[m][j0][0], acc2[m][j0][1]));
                a3f[kt][1] = maxbf2(pkbf(acc2[m][j0][2], acc2[m][j0][3]));
                a3f[kt][2] = maxbf2(pkbf(acc2[m][j1][0], acc2[m][j1][1]));
                a3f[kt][3] = maxbf2(pkbf(acc2[m][j1][2], acc2[m][j1][3]));
            }
            float acc3[2][4];
            #pragma unroll
            for (int nt = 0; nt < 2; nt++) {
                acc3[nt][0] = b3v[nt][0];
                acc3[nt][1] = b3v[nt][1];
                acc3[nt][2] = b3v[nt][0];
                acc3[nt][3] = b3v[nt][1];
            }
            #pragma unroll
            for (int kt = 0; kt < 2; kt++)
                #pragma unroll
                for (int nt = 0; nt < 2; nt++)
                    mma16816(acc3[nt], a3f[kt], rB3[kt][nt].x, rB3[kt][nt].y);

            float dpg, dph;
            dpg  = relu(acc3[0][0]) * w4c0;
            dpg  = fmaf(relu(acc3[0][1]), w4c1, dpg);
            dpg  = fmaf(relu(acc3[1][0]), w4c2, dpg);
            dpg  = fmaf(relu(acc3[1][1]), w4c3, dpg);
            dph  = relu(acc3[0][2]) * w4c0;
            dph  = fmaf(relu(acc3[0][3]), w4c1, dph);
            dph  = fmaf(relu(acc3[1][2]), w4c2, dph);
            dph  = fmaf(relu(acc3[1][3]), w4c3, dph);
            dpg += __shfl_xor_sync(0xffffffffu, dpg, 1);
            dpg += __shfl_xor_sync(0xffffffffu, dpg, 2);
            dph += __shfl_xor_sync(0xffffffffu, dph, 1);
            dph += __shfl_xor_sync(0xffffffffu, dph, 2);

            float wg = __shfl_sync(0xffffffffu, wide, m * 16 + g);
            float wh = __shfl_sync(0xffffffffu, wide, m * 16 + 8 + g);
            if (t4 == 0) {
                float zg = wg + dpg + sSc[0];
                float zh = wh + dph + sSc[0];
                out[R + m * 16 + g]     = __fdividef(1.f, 1.f + __expf(-zg));
                out[R + m * 16 + 8 + g] = __fdividef(1.f, 1.f + __expf(-zh));
            }
        }
    }
}

extern "C" void kernel_launch(void* const* d_in, const int* in_sizes, int n_in,
                              void* d_out, int out_size) {
    const int*   uids   = (const int*)  d_in[0];
    const int*   mids   = (const int*)  d_in[1];
    const float* gender = (const float*)d_in[2];
    const float* age    = (const float*)d_in[3];
    const float* occ    = (const float*)d_in[4];
    const float* genres = (const float*)d_in[5];
    const float* wideW  = (const float*)d_in[6];
    const float* wideB  = (const float*)d_in[7];
    const float* utab   = (const float*)d_in[8];
    const float* mtab   = (const float*)d_in[9];
    const float* W1     = (const float*)d_in[10];
    const float* b1     = (const float*)d_in[11];
    const float* W2     = (const float*)d_in[12];
    const float* b2     = (const float*)d_in[13];
    const float* W3     = (const float*)d_in[14];
    const float* b3     = (const float*)d_in[15];
    const float* W4     = (const float*)d_in[16];
    const float* b4     = (const float*)d_in[17];
    float* out = (float*)d_out;

    static int inited = 0;
    if (!inited) {
        cudaFuncSetAttribute(wd_mma, cudaFuncAttributeMaxDynamicSharedMemorySize, SMEM_BYTES);
        inited = 1;
    }

    prep_kernel<<<148, 256>>>(W1, W2, W3, b1, utab, mtab, wideW);
    wd_mma<<<GRID, THREADS, SMEM_BYTES>>>(uids, mids, gender, age, occ, genres,
                                          wideW, wideB, b2, b3, W4, b4, out);
}